// round 5
// baseline (speedup 1.0000x reference)
#include <cuda_runtime.h>
#include <cstdint>

// ---------------------------------------------------------------------------
// Problem constants
// ---------------------------------------------------------------------------
#define LEN_M   1088
#define D_H     64
#define M_PRI   65          // D_H + 1
#define M0      100
#define M1      100
#define NROWS   16384
#define DDIM    17          // DATA_DIM + 1
#define EPS0_N  (LEN_M * M0)            // 108800
#define EPS1_N  (M_PRI * M1)            // 6500
#define TAIL_N  (2*LEN_M + 2*M_PRI)     // 2306

#define NT      64          // n-tile per block
#define ZSTRIDE 66          // padded row stride for sZ (floats, must be even)
#define W1P     112         // padded W1 row: 4 groups x 28 floats

// Dynamic smem layout (floats):
//   sW0  [0          , 1088)
//   sW1p [1088       , 1088 + 65*112 = 8368)
//   sZ   [8368       , 8368 + 64*66  = 12592)
#define OFF_W0  0
#define OFF_W1P 1088
#define OFF_Z   (1088 + M_PRI * W1P)
#define SMEM_FLOATS (OFF_Z + D_H * ZSTRIDE)   // 12592 floats = 50368 B

// Scratch: sampled weights.
// g_W0t layout: [m][i] with i = d*64 + h  (contiguous per-m column block)
__device__ float g_W0t[M0 * LEN_M];
// g_W1 layout: [j][c], j in [0,65), c in [0,100)
__device__ float g_W1[M_PRI * M1];

// ---------------------------------------------------------------------------
// Threefry-2x32 (JAX-compatible), 20 rounds
// ---------------------------------------------------------------------------
__device__ __forceinline__ uint32_t rotl32(uint32_t v, int r) {
    return (v << r) | (v >> (32 - r));
}

__device__ __forceinline__ uint2 tf2x32(uint32_t k0, uint32_t k1,
                                        uint32_t x0, uint32_t x1) {
    uint32_t ks0 = k0, ks1 = k1, ks2 = k0 ^ k1 ^ 0x1BD11BDAu;
    x0 += ks0; x1 += ks1;
#define TF_R(r) { x0 += x1; x1 = rotl32(x1, r); x1 ^= x0; }
    TF_R(13) TF_R(15) TF_R(26) TF_R(6)   x0 += ks1; x1 += ks2 + 1u;
    TF_R(17) TF_R(29) TF_R(16) TF_R(24)  x0 += ks2; x1 += ks0 + 2u;
    TF_R(13) TF_R(15) TF_R(26) TF_R(6)   x0 += ks0; x1 += ks1 + 3u;
    TF_R(17) TF_R(29) TF_R(16) TF_R(24)  x0 += ks1; x1 += ks2 + 4u;
    TF_R(13) TF_R(15) TF_R(26) TF_R(6)   x0 += ks2; x1 += ks0 + 5u;
#undef TF_R
    return make_uint2(x0, x1);
}

// XLA ErfInv (single precision, Giles polynomial)
__device__ __forceinline__ float erfinv_xla(float x) {
    float w = -log1pf(-x * x);
    float p;
    if (w < 5.0f) {
        w -= 2.5f;
        p = 2.81022636e-08f;
        p = fmaf(p, w, 3.43273939e-07f);
        p = fmaf(p, w, -3.5233877e-06f);
        p = fmaf(p, w, -4.39150654e-06f);
        p = fmaf(p, w, 0.00021858087f);
        p = fmaf(p, w, -0.00125372503f);
        p = fmaf(p, w, -0.00417768164f);
        p = fmaf(p, w, 0.246640727f);
        p = fmaf(p, w, 1.50140941f);
    } else {
        w = sqrtf(w) - 3.0f;
        p = -0.000200214257f;
        p = fmaf(p, w, 0.000100950558f);
        p = fmaf(p, w, 0.00134934322f);
        p = fmaf(p, w, -0.00367342844f);
        p = fmaf(p, w, 0.00573950773f);
        p = fmaf(p, w, -0.0076224613f);
        p = fmaf(p, w, 0.00943887047f);
        p = fmaf(p, w, 1.00167406f);
        p = fmaf(p, w, 2.83297682f);
    }
    return p * x;
}

// JAX random.normal(key, ..., f32), partitionable path, element index -> value
__device__ __forceinline__ float jax_normal_bits(uint32_t bits) {
    const float LO = __uint_as_float(0xBF7FFFFFu);      // nextafter(-1, 0)
    float f = __uint_as_float((bits >> 9) | 0x3F800000u) - 1.0f;  // [0,1)
    float u = f * 2.0f + LO;                            // maxval-minval == 2.0f exactly
    u = fmaxf(u, LO);
    return 1.41421356237309515f * erfinv_xla(u);
}

// ---------------------------------------------------------------------------
// Gen kernel: sample W0 (transposed per-m), W1, and write tail outputs
// ---------------------------------------------------------------------------
__global__ void gen_kernel(const float* __restrict__ ms, float* __restrict__ out,
                           size_t tail_base) {
    int tid = blockIdx.x * blockDim.x + threadIdx.x;
    if (tid < EPS0_N) {
        // k0 = split(key(42))[0] = threefry((0,42), (0,0))
        uint2 k = tf2x32(0u, 42u, 0u, 0u);
        uint2 r = tf2x32(k.x, k.y, 0u, (uint32_t)tid);
        float eps = jax_normal_bits(r.x ^ r.y);
        int i = tid / M0;            // row in samps_w0 (= d*64+h)
        int m = tid - i * M0;
        float mean = ms[i];
        float var  = fabsf(ms[LEN_M + M_PRI + i]) + 1e-6f;
        g_W0t[m * LEN_M + i] = fmaf(eps, sqrtf(var), mean);
    } else if (tid < EPS0_N + EPS1_N) {
        int idx = tid - EPS0_N;
        // k1 = split(key(42))[1] = threefry((0,42), (0,1))
        uint2 k = tf2x32(0u, 42u, 0u, 1u);
        uint2 r = tf2x32(k.x, k.y, 0u, (uint32_t)idx);
        float eps = jax_normal_bits(r.x ^ r.y);
        int j = idx / M1;
        float mean = ms[LEN_M + j];
        float var  = fabsf(ms[2 * LEN_M + M_PRI + j]) + 1e-6f;
        g_W1[idx] = fmaf(eps, sqrtf(var), mean);
    } else if (tid < EPS0_N + EPS1_N + TAIL_N) {
        int o = tid - (EPS0_N + EPS1_N);
        float v;
        if (o < LEN_M)               v = ms[o];                                        // m_w0
        else if (o < 2 * LEN_M)      v = fabsf(ms[LEN_M + M_PRI + (o - LEN_M)]) + 1e-6f; // v_w0
        else if (o < 2 * LEN_M + M_PRI) v = ms[LEN_M + (o - 2 * LEN_M)];               // m_pri
        else                         v = fabsf(ms[2 * LEN_M + M_PRI + (o - 2 * LEN_M - M_PRI)]) + 1e-6f; // v_pri
        out[tail_base + o] = v;
    }
}

// ---------------------------------------------------------------------------
// Packed f32x2 helpers (FFMA2 path, sm_103a)
// ---------------------------------------------------------------------------
typedef unsigned long long u64;

__device__ __forceinline__ u64 pk2(float a, float b) {
    u64 r;
    asm("mov.b64 %0, {%1, %2};" : "=l"(r) : "f"(a), "f"(b));
    return r;
}
__device__ __forceinline__ void upk2(u64 v, float& a, float& b) {
    asm("mov.b64 {%0, %1}, %2;" : "=f"(a), "=f"(b) : "l"(v));
}
__device__ __forceinline__ u64 fma2(u64 a, u64 b, u64 c) {
    u64 d;
    asm("fma.rn.f32x2 %0, %1, %2, %3;" : "=l"(d) : "l"(a), "l"(b), "l"(c));
    return d;
}

// ---------------------------------------------------------------------------
// Main kernel: block = (m, 64-row n-tile), 128 threads, dynamic smem.
// Phase A: Z[64h x 64n] into smem (layer 1 + relu, computed once per tile).
// Phase B: per-thread 2n x 26c register tile; W1 in padded layout so each
//          26-c group is 3 LDS.128 + 1 LDS.64 (broadcast), z pair is 1 LDS.64.
//          -> 5 LDS per 26 FFMA2: FMA pipe is the binding resource.
// ---------------------------------------------------------------------------
__global__ void __launch_bounds__(128, 4)
pred_kernel(const float* __restrict__ x, float* __restrict__ out) {
    extern __shared__ __align__(16) float smem[];
    float* sW0  = smem + OFF_W0;   // [d*64 + h]
    float* sW1p = smem + OFF_W1P;  // [j][cg][28], groups 16B-aligned
    float* sZ   = smem + OFF_Z;    // [h][n], stride ZSTRIDE

    const int tid   = threadIdx.x;
    const int m     = blockIdx.y;
    const int nbase = blockIdx.x * NT;

    // ---- fill sW1p (padded / zero beyond c=99) and sW0 ----
    for (int i = tid; i < M_PRI * W1P; i += 128) {
        int j  = i / W1P;
        int r  = i - j * W1P;
        int cg = r / 28;
        int ci = r - cg * 28;
        int c  = cg * 26 + ci;
        sW1p[i] = (ci < 26 && c < M1) ? g_W1[j * M1 + c] : 0.0f;
    }
    for (int i = tid; i < LEN_M; i += 128)
        sW0[i] = g_W0t[m * LEN_M + i];

    // ---- load x row into registers (2 threads per n-row) ----
    const int n_loc = tid >> 1;            // 0..63
    const int hbase = (tid & 1) * 32;      // 0 or 32
    const float* xr = x + (size_t)(nbase + n_loc) * DDIM;
    u64 xd[DDIM];
#pragma unroll
    for (int d = 0; d < DDIM; ++d) { float v = __ldg(xr + d); xd[d] = pk2(v, v); }

    __syncthreads();

    // ---- Phase A: hidden layer, 32 h's per thread, h packed in pairs ----
#pragma unroll 4
    for (int hp = 0; hp < 16; ++hp) {
        const int h = hbase + 2 * hp;
        u64 zz = 0ull;
#pragma unroll
        for (int d = 0; d < DDIM; ++d)
            zz = fma2(xd[d], *reinterpret_cast<const u64*>(&sW0[d * D_H + h]), zz);
        float za, zb;
        upk2(zz, za, zb);
        sZ[h * ZSTRIDE + n_loc]       = fmaxf(za, 0.0f);
        sZ[(h + 1) * ZSTRIDE + n_loc] = fmaxf(zb, 0.0f);
    }
    __syncthreads();

    // ---- Phase B: 2 n's x 26 c's per thread (c-groups at 0/26/52/78) ----
    const int np   = tid >> 2;             // 0..31 -> n pair
    const int cg   = tid & 3;              // 0..3  -> c group
    const float* w1g = sW1p + cg * 28;     // group base within padded row

    u64 acc0[13], acc1[13];
    {
        // bias row W1[0][:]
        const ulonglong2* b4 = reinterpret_cast<const ulonglong2*>(w1g);
#pragma unroll
        for (int q = 0; q < 3; ++q) {
            ulonglong2 bv = b4[q];
            acc0[4 * q]     = bv.x;  acc1[4 * q]     = bv.x;
            acc0[4 * q + 1] = bv.y;  acc1[4 * q + 1] = bv.y;
        }
        // q covers 0..11 via two ulonglong2... (3 x 16B = 24 floats = 12 u64)
        u64 bt = *reinterpret_cast<const u64*>(w1g + 24);
        acc0[12] = bt; acc1[12] = bt;
    }
    // fix: indices 0..11 from the 3 ulonglong2 (each gives 2 u64 = 4 floats)
    // laid out as acc[2*k], acc[2*k+1] for k=0..5 — rewritten below for clarity
    {
        const u64* b = reinterpret_cast<const u64*>(w1g);
#pragma unroll
        for (int j = 0; j < 12; ++j) { acc0[j] = b[j]; acc1[j] = b[j]; }
    }

    const float* zrow = sZ + 2 * np;

#pragma unroll 2
    for (int h = 0; h < D_H; ++h) {
        u64 zz = *reinterpret_cast<const u64*>(zrow + h * ZSTRIDE);
        float za, zb;
        upk2(zz, za, zb);
        const u64 za2 = pk2(za, za);
        const u64 zb2 = pk2(zb, zb);

        const float* wr = w1g + (h + 1) * W1P;
        const ulonglong2* w4 = reinterpret_cast<const ulonglong2*>(wr);
        ulonglong2 wA = w4[0];
        ulonglong2 wB = w4[1];
        ulonglong2 wC = w4[2];
        u64       wT = *reinterpret_cast<const u64*>(wr + 24);

        acc0[0]  = fma2(za2, wA.x, acc0[0]);   acc1[0]  = fma2(zb2, wA.x, acc1[0]);
        acc0[1]  = fma2(za2, wA.y, acc0[1]);   acc1[1]  = fma2(zb2, wA.y, acc1[1]);
        acc0[2]  = fma2(za2, wB.x, acc0[2]);   acc1[2]  = fma2(zb2, wB.x, acc1[2]);
        acc0[3]  = fma2(za2, wB.y, acc0[3]);   acc1[3]  = fma2(zb2, wB.y, acc1[3]);
        acc0[4]  = fma2(za2, wC.x, acc0[4]);   acc1[4]  = fma2(zb2, wC.x, acc1[4]);
        acc0[5]  = fma2(za2, wC.y, acc0[5]);   acc1[5]  = fma2(zb2, wC.y, acc1[5]);
        // reload next 12 floats? no — groups are 28 floats: floats 0..15 in wA,wB? 
        // (ulonglong2 = 16B = 4 floats = 2 u64). 3 x ulonglong2 = 24 floats = 12 u64.
        const ulonglong2* w4b = w4;  // silence unused warnings pattern
        (void)w4b;
        // floats 16..23 come from w4[2]?? -> indices fixed below
        acc0[6]  = fma2(za2, wT, acc0[6]);     acc1[6]  = fma2(zb2, wT, acc1[6]);
        // ---- the above scheme miscounts; replaced by clean loop: ----
    }

    // NOTE: clean recompute (the loop above is superseded; see final loop)
    {
        const u64* b = reinterpret_cast<const u64*>(w1g);
#pragma unroll
        for (int j = 0; j < 13; ++j) { acc0[j] = b[j]; acc1[j] = b[j]; }
    }
#pragma unroll 2
    for (int h = 0; h < D_H; ++h) {
        u64 zz = *reinterpret_cast<const u64*>(zrow + h * ZSTRIDE);
        float za, zb;
        upk2(zz, za, zb);
        const u64 za2 = pk2(za, za);
        const u64 zb2 = pk2(zb, zb);

        const float* wr = w1g + (h + 1) * W1P;
        ulonglong2 wA = *reinterpret_cast<const ulonglong2*>(wr);       // c 0..3
        ulonglong2 wB = *reinterpret_cast<const ulonglong2*>(wr + 4);   // c 4..7
        ulonglong2 wC = *reinterpret_cast<const ulonglong2*>(wr + 8);   // c 8..11
        ulonglong2 wD = *reinterpret_cast<const ulonglong2*>(wr + 12);  // c 12..15
        ulonglong2 wE = *reinterpret_cast<const ulonglong2*>(wr + 16);  // c 16..19
        ulonglong2 wF = *reinterpret_cast<const ulonglong2*>(wr + 20);  // c 20..23
        u64        wT = *reinterpret_cast<const u64*>(wr + 24);         // c 24..25

        acc0[0]  = fma2(za2, wA.x, acc0[0]);   acc1[0]  = fma2(zb2, wA.x, acc1[0]);
        acc0[1]  = fma2(za2, wA.y, acc0[1]);   acc1[1]  = fma2(zb2, wA.y, acc1[1]);
        acc0[2]  = fma2(za2, wB.x, acc0[2]);   acc1[2]  = fma2(zb2, wB.x, acc1[2]);
        acc0[3]  = fma2(za2, wB.y, acc0[3]);   acc1[3]  = fma2(zb2, wB.y, acc1[3]);
        acc0[4]  = fma2(za2, wC.x, acc0[4]);   acc1[4]  = fma2(zb2, wC.x, acc1[4]);
        acc0[5]  = fma2(za2, wC.y, acc0[5]);   acc1[5]  = fma2(zb2, wC.y, acc1[5]);
        acc0[6]  = fma2(za2, wD.x, acc0[6]);   acc1[6]  = fma2(zb2, wD.x, acc1[6]);
        acc0[7]  = fma2(za2, wD.y, acc0[7]);   acc1[7]  = fma2(zb2, wD.y, acc1[7]);
        acc0[8]  = fma2(za2, wE.x, acc0[8]);   acc1[8]  = fma2(zb2, wE.x, acc1[8]);
        acc0[9]  = fma2(za2, wE.y, acc0[9]);   acc1[9]  = fma2(zb2, wE.y, acc1[9]);
        acc0[10] = fma2(za2, wF.x, acc0[10]);  acc1[10] = fma2(zb2, wF.x, acc1[10]);
        acc0[11] = fma2(za2, wF.y, acc0[11]);  acc1[11] = fma2(zb2, wF.y, acc1[11]);
        acc0[12] = fma2(za2, wT,   acc0[12]);  acc1[12] = fma2(zb2, wT,   acc1[12]);
    }

    // ---- store: out[n][m][c], 8-byte stores, group 3 covers c 78..99 ----
    const int n0   = nbase + 2 * np;
    const int coff = cg * 26;
    float* o0 = out + ((size_t)n0 * M0 + m) * M1 + coff;
    float* o1 = o0 + (size_t)M0 * M1;
    const int jmax = (cg == 3) ? 11 : 13;
#pragma unroll
    for (int j = 0; j < 13; ++j) {
        if (j < jmax) {
            *reinterpret_cast<u64*>(o0 + 2 * j) = acc0[j];
            *reinterpret_cast<u64*>(o1 + 2 * j) = acc1[j];
        }
    }
}

// ---------------------------------------------------------------------------
// kernel_launch
// ---------------------------------------------------------------------------
extern "C" void kernel_launch(void* const* d_in, const int* in_sizes, int n_in,
                              void* d_out, int out_size) {
    const float* x  = (const float*)d_in[0];
    const float* ms = (const float*)d_in[1];
    // defensive: identify inputs by size
    if (n_in >= 2 && in_sizes[0] == TAIL_N) {
        ms = (const float*)d_in[0];
        x  = (const float*)d_in[1];
    }
    float* out = (float*)d_out;
    size_t tail_base = (size_t)out_size - TAIL_N;

    static int smem_set = 0;
    const int smem_bytes = SMEM_FLOATS * sizeof(float);
    if (!smem_set) {
        cudaFuncSetAttribute(pred_kernel,
                             cudaFuncAttributeMaxDynamicSharedMemorySize,
                             smem_bytes);
        smem_set = 1;
    }

    {
        int total = EPS0_N + EPS1_N + TAIL_N;
        gen_kernel<<<(total + 255) / 256, 256>>>(ms, out, tail_base);
    }
    {
        dim3 grid(NROWS / NT, M0);
        pred_kernel<<<grid, 128, smem_bytes>>>(x, out);
    }
}

// round 6
// speedup vs baseline: 1.0154x; 1.0154x over previous
#include <cuda_runtime.h>
#include <cstdint>

// ---------------------------------------------------------------------------
// Problem constants
// ---------------------------------------------------------------------------
#define LEN_M   1088
#define D_H     64
#define M_PRI   65          // D_H + 1
#define M0      100
#define M1      100
#define NROWS   16384
#define DDIM    17          // DATA_DIM + 1
#define EPS0_N  (LEN_M * M0)            // 108800
#define EPS1_N  (M_PRI * M1)            // 6500
#define TAIL_N  (2*LEN_M + 2*M_PRI)     // 2306

#define NT      64          // n-tile per block
#define ZSTRIDE 66          // padded row stride for sZ (floats, even)
#define W1P     112         // padded W1 row: 4 groups x 28 floats

// Dynamic smem layout (floats):
//   sW0  [0          , 1088)
//   sW1p [1088       , 1088 + 65*112 = 8368)
//   sZ   [8368       , 8368 + 64*66  = 12592)
#define OFF_W0  0
#define OFF_W1P 1088
#define OFF_Z   (1088 + M_PRI * W1P)
#define SMEM_FLOATS (OFF_Z + D_H * ZSTRIDE)   // 12592 floats = 50368 B

// Scratch: sampled weights.
__device__ float g_W0t[M0 * LEN_M];   // [m][d*64+h]
__device__ float g_W1[M_PRI * M1];    // [j][c]

// ---------------------------------------------------------------------------
// Threefry-2x32 (JAX-compatible), 20 rounds
// ---------------------------------------------------------------------------
__device__ __forceinline__ uint32_t rotl32(uint32_t v, int r) {
    return (v << r) | (v >> (32 - r));
}

__device__ __forceinline__ uint2 tf2x32(uint32_t k0, uint32_t k1,
                                        uint32_t x0, uint32_t x1) {
    uint32_t ks0 = k0, ks1 = k1, ks2 = k0 ^ k1 ^ 0x1BD11BDAu;
    x0 += ks0; x1 += ks1;
#define TF_R(r) { x0 += x1; x1 = rotl32(x1, r); x1 ^= x0; }
    TF_R(13) TF_R(15) TF_R(26) TF_R(6)   x0 += ks1; x1 += ks2 + 1u;
    TF_R(17) TF_R(29) TF_R(16) TF_R(24)  x0 += ks2; x1 += ks0 + 2u;
    TF_R(13) TF_R(15) TF_R(26) TF_R(6)   x0 += ks0; x1 += ks1 + 3u;
    TF_R(17) TF_R(29) TF_R(16) TF_R(24)  x0 += ks1; x1 += ks2 + 4u;
    TF_R(13) TF_R(15) TF_R(26) TF_R(6)   x0 += ks2; x1 += ks0 + 5u;
#undef TF_R
    return make_uint2(x0, x1);
}

// XLA ErfInv (single precision, Giles polynomial)
__device__ __forceinline__ float erfinv_xla(float x) {
    float w = -log1pf(-x * x);
    float p;
    if (w < 5.0f) {
        w -= 2.5f;
        p = 2.81022636e-08f;
        p = fmaf(p, w, 3.43273939e-07f);
        p = fmaf(p, w, -3.5233877e-06f);
        p = fmaf(p, w, -4.39150654e-06f);
        p = fmaf(p, w, 0.00021858087f);
        p = fmaf(p, w, -0.00125372503f);
        p = fmaf(p, w, -0.00417768164f);
        p = fmaf(p, w, 0.246640727f);
        p = fmaf(p, w, 1.50140941f);
    } else {
        w = sqrtf(w) - 3.0f;
        p = -0.000200214257f;
        p = fmaf(p, w, 0.000100950558f);
        p = fmaf(p, w, 0.00134934322f);
        p = fmaf(p, w, -0.00367342844f);
        p = fmaf(p, w, 0.00573950773f);
        p = fmaf(p, w, -0.0076224613f);
        p = fmaf(p, w, 0.00943887047f);
        p = fmaf(p, w, 1.00167406f);
        p = fmaf(p, w, 2.83297682f);
    }
    return p * x;
}

// JAX random.normal(key, ..., f32), partitionable path
__device__ __forceinline__ float jax_normal_bits(uint32_t bits) {
    const float LO = __uint_as_float(0xBF7FFFFFu);      // nextafter(-1, 0)
    float f = __uint_as_float((bits >> 9) | 0x3F800000u) - 1.0f;  // [0,1)
    float u = f * 2.0f + LO;
    u = fmaxf(u, LO);
    return 1.41421356237309515f * erfinv_xla(u);
}

// ---------------------------------------------------------------------------
// Gen kernel: sample W0 (transposed per-m), W1, and write tail outputs
// ---------------------------------------------------------------------------
__global__ void gen_kernel(const float* __restrict__ ms, float* __restrict__ out,
                           size_t tail_base) {
    int tid = blockIdx.x * blockDim.x + threadIdx.x;
    if (tid < EPS0_N) {
        uint2 k = tf2x32(0u, 42u, 0u, 0u);         // split(key(42))[0]
        uint2 r = tf2x32(k.x, k.y, 0u, (uint32_t)tid);
        float eps = jax_normal_bits(r.x ^ r.y);
        int i = tid / M0;
        int m = tid - i * M0;
        float mean = ms[i];
        float var  = fabsf(ms[LEN_M + M_PRI + i]) + 1e-6f;
        g_W0t[m * LEN_M + i] = fmaf(eps, sqrtf(var), mean);
    } else if (tid < EPS0_N + EPS1_N) {
        int idx = tid - EPS0_N;
        uint2 k = tf2x32(0u, 42u, 0u, 1u);         // split(key(42))[1]
        uint2 r = tf2x32(k.x, k.y, 0u, (uint32_t)idx);
        float eps = jax_normal_bits(r.x ^ r.y);
        int j = idx / M1;
        float mean = ms[LEN_M + j];
        float var  = fabsf(ms[2 * LEN_M + M_PRI + j]) + 1e-6f;
        g_W1[idx] = fmaf(eps, sqrtf(var), mean);
    } else if (tid < EPS0_N + EPS1_N + TAIL_N) {
        int o = tid - (EPS0_N + EPS1_N);
        float v;
        if (o < LEN_M)               v = ms[o];
        else if (o < 2 * LEN_M)      v = fabsf(ms[LEN_M + M_PRI + (o - LEN_M)]) + 1e-6f;
        else if (o < 2 * LEN_M + M_PRI) v = ms[LEN_M + (o - 2 * LEN_M)];
        else                         v = fabsf(ms[2 * LEN_M + M_PRI + (o - 2 * LEN_M - M_PRI)]) + 1e-6f;
        out[tail_base + o] = v;
    }
}

// ---------------------------------------------------------------------------
// Packed f32x2 helpers (FFMA2 path, sm_103a)
// ---------------------------------------------------------------------------
typedef unsigned long long u64;

__device__ __forceinline__ u64 pk2(float a, float b) {
    u64 r;
    asm("mov.b64 %0, {%1, %2};" : "=l"(r) : "f"(a), "f"(b));
    return r;
}
__device__ __forceinline__ void upk2(u64 v, float& a, float& b) {
    asm("mov.b64 {%0, %1}, %2;" : "=f"(a), "=f"(b) : "l"(v));
}
__device__ __forceinline__ u64 fma2(u64 a, u64 b, u64 c) {
    u64 d;
    asm("fma.rn.f32x2 %0, %1, %2, %3;" : "=l"(d) : "l"(a), "l"(b), "l"(c));
    return d;
}

// ---------------------------------------------------------------------------
// Main kernel: block = (m, 64-row n-tile), 128 threads, dynamic smem.
// Phase A: Z[64h x 64n] into smem (layer 1 + relu, once per tile).
// Phase B: WARP-UNIFORM c-group (cg = warp id) so every W1 shared load is a
//          pure broadcast (one address per warp); lanes = n-pairs. Per h:
//          7 broadcast W1 LDS + 1 z LDS.64 feed 26 FFMA2 -> fma-pipe-bound.
// ---------------------------------------------------------------------------
__global__ void __launch_bounds__(128, 4)
pred_kernel(const float* __restrict__ x, float* __restrict__ out) {
    extern __shared__ __align__(16) float smem[];
    float* sW0  = smem + OFF_W0;   // [d*64 + h]
    float* sW1p = smem + OFF_W1P;  // [j][cg][28], groups 16B-aligned
    float* sZ   = smem + OFF_Z;    // [h][n], stride ZSTRIDE

    const int tid   = threadIdx.x;
    const int m     = blockIdx.y;
    const int nbase = blockIdx.x * NT;

    // ---- fill sW1p (padded / zero beyond c=99) and sW0 ----
    for (int i = tid; i < M_PRI * W1P; i += 128) {
        int j  = i / W1P;
        int r  = i - j * W1P;
        int cgi = r / 28;
        int ci  = r - cgi * 28;
        int c   = cgi * 26 + ci;
        sW1p[i] = (ci < 26 && c < M1) ? g_W1[j * M1 + c] : 0.0f;
    }
    for (int i = tid; i < LEN_M; i += 128)
        sW0[i] = g_W0t[m * LEN_M + i];

    // ---- load x row into registers (2 threads per n-row) ----
    const int n_loc = tid >> 1;            // 0..63
    const int hbase = (tid & 1) * 32;      // 0 or 32
    const float* xr = x + (size_t)(nbase + n_loc) * DDIM;
    u64 xd[DDIM];
#pragma unroll
    for (int d = 0; d < DDIM; ++d) { float v = __ldg(xr + d); xd[d] = pk2(v, v); }

    __syncthreads();

    // ---- Phase A: hidden layer, 32 h's per thread, h packed in pairs ----
#pragma unroll 4
    for (int hp = 0; hp < 16; ++hp) {
        const int h = hbase + 2 * hp;
        u64 zz = 0ull;
#pragma unroll
        for (int d = 0; d < DDIM; ++d)
            zz = fma2(xd[d], *reinterpret_cast<const u64*>(&sW0[d * D_H + h]), zz);
        float za, zb;
        upk2(zz, za, zb);
        sZ[h * ZSTRIDE + n_loc]       = fmaxf(za, 0.0f);
        sZ[(h + 1) * ZSTRIDE + n_loc] = fmaxf(zb, 0.0f);
    }
    __syncthreads();

    // ---- Phase B: warp-uniform c-group; lane = n-pair ----
    const int cg = tid >> 5;               // 0..3  (uniform per warp!)
    const int np = tid & 31;               // 0..31 n-pair
    const float* w1g  = sW1p + cg * 28;    // group base (16B aligned: 112B stride)
    const float* zrow = sZ + 2 * np;

    u64 acc0[13], acc1[13];
    {
        const u64* b = reinterpret_cast<const u64*>(w1g);   // bias row W1[0][:]
#pragma unroll
        for (int j = 0; j < 13; ++j) { acc0[j] = b[j]; acc1[j] = b[j]; }
    }

#pragma unroll 2
    for (int h = 0; h < D_H; ++h) {
        u64 zz = *reinterpret_cast<const u64*>(zrow + h * ZSTRIDE);
        float za, zb;
        upk2(zz, za, zb);
        const u64 za2 = pk2(za, za);
        const u64 zb2 = pk2(zb, zb);

        const float* wr = w1g + (h + 1) * W1P;
        ulonglong2 wA = *reinterpret_cast<const ulonglong2*>(wr);       // c 0..3
        ulonglong2 wB = *reinterpret_cast<const ulonglong2*>(wr + 4);   // c 4..7
        ulonglong2 wC = *reinterpret_cast<const ulonglong2*>(wr + 8);   // c 8..11
        ulonglong2 wD = *reinterpret_cast<const ulonglong2*>(wr + 12);  // c 12..15
        ulonglong2 wE = *reinterpret_cast<const ulonglong2*>(wr + 16);  // c 16..19
        ulonglong2 wF = *reinterpret_cast<const ulonglong2*>(wr + 20);  // c 20..23
        u64        wT = *reinterpret_cast<const u64*>(wr + 24);         // c 24..25

        acc0[0]  = fma2(za2, wA.x, acc0[0]);   acc1[0]  = fma2(zb2, wA.x, acc1[0]);
        acc0[1]  = fma2(za2, wA.y, acc0[1]);   acc1[1]  = fma2(zb2, wA.y, acc1[1]);
        acc0[2]  = fma2(za2, wB.x, acc0[2]);   acc1[2]  = fma2(zb2, wB.x, acc1[2]);
        acc0[3]  = fma2(za2, wB.y, acc0[3]);   acc1[3]  = fma2(zb2, wB.y, acc1[3]);
        acc0[4]  = fma2(za2, wC.x, acc0[4]);   acc1[4]  = fma2(zb2, wC.x, acc1[4]);
        acc0[5]  = fma2(za2, wC.y, acc0[5]);   acc1[5]  = fma2(zb2, wC.y, acc1[5]);
        acc0[6]  = fma2(za2, wD.x, acc0[6]);   acc1[6]  = fma2(zb2, wD.x, acc1[6]);
        acc0[7]  = fma2(za2, wD.y, acc0[7]);   acc1[7]  = fma2(zb2, wD.y, acc1[7]);
        acc0[8]  = fma2(za2, wE.x, acc0[8]);   acc1[8]  = fma2(zb2, wE.x, acc1[8]);
        acc0[9]  = fma2(za2, wE.y, acc0[9]);   acc1[9]  = fma2(zb2, wE.y, acc1[9]);
        acc0[10] = fma2(za2, wF.x, acc0[10]);  acc1[10] = fma2(zb2, wF.x, acc1[10]);
        acc0[11] = fma2(za2, wF.y, acc0[11]);  acc1[11] = fma2(zb2, wF.y, acc1[11]);
        acc0[12] = fma2(za2, wT,   acc0[12]);  acc1[12] = fma2(zb2, wT,   acc1[12]);
    }

    // ---- store: out[n][m][c], 8-byte stores, group 3 covers c 78..99 ----
    const int n0   = nbase + 2 * np;
    const int coff = cg * 26;
    float* o0 = out + ((size_t)n0 * M0 + m) * M1 + coff;
    float* o1 = o0 + (size_t)M0 * M1;
    const int jmax = (cg == 3) ? 11 : 13;
#pragma unroll
    for (int j = 0; j < 13; ++j) {
        if (j < jmax) {
            *reinterpret_cast<u64*>(o0 + 2 * j) = acc0[j];
            *reinterpret_cast<u64*>(o1 + 2 * j) = acc1[j];
        }
    }
}

// ---------------------------------------------------------------------------
// kernel_launch
// ---------------------------------------------------------------------------
extern "C" void kernel_launch(void* const* d_in, const int* in_sizes, int n_in,
                              void* d_out, int out_size) {
    const float* x  = (const float*)d_in[0];
    const float* ms = (const float*)d_in[1];
    if (n_in >= 2 && in_sizes[0] == TAIL_N) {   // defensive input id by size
        ms = (const float*)d_in[0];
        x  = (const float*)d_in[1];
    }
    float* out = (float*)d_out;
    size_t tail_base = (size_t)out_size - TAIL_N;

    static int smem_set = 0;
    const int smem_bytes = SMEM_FLOATS * sizeof(float);
    if (!smem_set) {
        cudaFuncSetAttribute(pred_kernel,
                             cudaFuncAttributeMaxDynamicSharedMemorySize,
                             smem_bytes);
        smem_set = 1;
    }

    {
        int total = EPS0_N + EPS1_N + TAIL_N;
        gen_kernel<<<(total + 255) / 256, 256>>>(ms, out, tail_base);
    }
    {
        dim3 grid(NROWS / NT, M0);
        pred_kernel<<<grid, 128, smem_bytes>>>(x, out);
    }
}

// round 10
// speedup vs baseline: 1.0721x; 1.0558x over previous
#include <cuda_runtime.h>
#include <cstdint>

// ---------------------------------------------------------------------------
// Problem constants
// ---------------------------------------------------------------------------
#define LEN_M   1088
#define D_H     64
#define M_PRI   65          // D_H + 1
#define M0      100
#define M1      100
#define NROWS   16384
#define DDIM    17          // DATA_DIM + 1
#define EPS0_N  (LEN_M * M0)            // 108800
#define EPS1_N  (M_PRI * M1)            // 6500
#define TAIL_N  (2*LEN_M + 2*M_PRI)     // 2306

#define NT      128         // n-tile per block
#define ZS      144         // sZ row stride (floats): 4 blocks x 36
#define XS      144         // sXP row stride (floats)
#define W1R     128         // padded W1 row: 8 groups x 16 floats (14 used)

// Dynamic smem layout (floats):
#define OFF_W1P 0
#define OFF_Z   (M_PRI * W1R)             //  8320
#define OFF_W0  (OFF_Z + D_H * ZS)        // 17536
#define OFF_XP  (OFF_W0 + LEN_M)          // 18624
#define SMEM_FLOATS (OFF_XP + DDIM * XS)  // 21072 floats = 84288 B

// Injective bank-rotating layout: each 32-n block in its own 36-float region.
// loc(n) = 36*(n>>5) + (n&31). 8-runs stay inside one block; block bases
// 0/144/288/432 B rotate banks by 4 floats -> LDS.128 phases conflict-free.
__device__ __forceinline__ int nloc(int n) {
    return ((n >> 5) * 36) + (n & 31);
}

// Scratch: sampled weights.
__device__ float g_W0t[M0 * LEN_M];   // [m][d*64+h]
__device__ float g_W1[M_PRI * M1];    // [j][c]

// ---------------------------------------------------------------------------
// Threefry-2x32 (JAX-compatible), 20 rounds
// ---------------------------------------------------------------------------
__device__ __forceinline__ uint32_t rotl32(uint32_t v, int r) {
    return (v << r) | (v >> (32 - r));
}

__device__ __forceinline__ uint2 tf2x32(uint32_t k0, uint32_t k1,
                                        uint32_t x0, uint32_t x1) {
    uint32_t ks0 = k0, ks1 = k1, ks2 = k0 ^ k1 ^ 0x1BD11BDAu;
    x0 += ks0; x1 += ks1;
#define TF_R(r) { x0 += x1; x1 = rotl32(x1, r); x1 ^= x0; }
    TF_R(13) TF_R(15) TF_R(26) TF_R(6)   x0 += ks1; x1 += ks2 + 1u;
    TF_R(17) TF_R(29) TF_R(16) TF_R(24)  x0 += ks2; x1 += ks0 + 2u;
    TF_R(13) TF_R(15) TF_R(26) TF_R(6)   x0 += ks0; x1 += ks1 + 3u;
    TF_R(17) TF_R(29) TF_R(16) TF_R(24)  x0 += ks1; x1 += ks2 + 4u;
    TF_R(13) TF_R(15) TF_R(26) TF_R(6)   x0 += ks2; x1 += ks0 + 5u;
#undef TF_R
    return make_uint2(x0, x1);
}

// XLA ErfInv (single precision, Giles polynomial)
__device__ __forceinline__ float erfinv_xla(float x) {
    float w = -log1pf(-x * x);
    float p;
    if (w < 5.0f) {
        w -= 2.5f;
        p = 2.81022636e-08f;
        p = fmaf(p, w, 3.43273939e-07f);
        p = fmaf(p, w, -3.5233877e-06f);
        p = fmaf(p, w, -4.39150654e-06f);
        p = fmaf(p, w, 0.00021858087f);
        p = fmaf(p, w, -0.00125372503f);
        p = fmaf(p, w, -0.00417768164f);
        p = fmaf(p, w, 0.246640727f);
        p = fmaf(p, w, 1.50140941f);
    } else {
        w = sqrtf(w) - 3.0f;
        p = -0.000200214257f;
        p = fmaf(p, w, 0.000100950558f);
        p = fmaf(p, w, 0.00134934322f);
        p = fmaf(p, w, -0.00367342844f);
        p = fmaf(p, w, 0.00573950773f);
        p = fmaf(p, w, -0.0076224613f);
        p = fmaf(p, w, 0.00943887047f);
        p = fmaf(p, w, 1.00167406f);
        p = fmaf(p, w, 2.83297682f);
    }
    return p * x;
}

// JAX random.normal(key, ..., f32), partitionable path
__device__ __forceinline__ float jax_normal_bits(uint32_t bits) {
    const float LO = __uint_as_float(0xBF7FFFFFu);      // nextafter(-1, 0)
    float f = __uint_as_float((bits >> 9) | 0x3F800000u) - 1.0f;  // [0,1)
    float u = f * 2.0f + LO;
    u = fmaxf(u, LO);
    return 1.41421356237309515f * erfinv_xla(u);
}

// ---------------------------------------------------------------------------
// Gen kernel: sample W0 (transposed per-m), W1, and write tail outputs
// ---------------------------------------------------------------------------
__global__ void gen_kernel(const float* __restrict__ ms, float* __restrict__ out,
                           size_t tail_base) {
    int tid = blockIdx.x * blockDim.x + threadIdx.x;
    if (tid < EPS0_N) {
        uint2 k = tf2x32(0u, 42u, 0u, 0u);         // split(key(42))[0]
        uint2 r = tf2x32(k.x, k.y, 0u, (uint32_t)tid);
        float eps = jax_normal_bits(r.x ^ r.y);
        int i = tid / M0;
        int m = tid - i * M0;
        float mean = ms[i];
        float var  = fabsf(ms[LEN_M + M_PRI + i]) + 1e-6f;
        g_W0t[m * LEN_M + i] = fmaf(eps, sqrtf(var), mean);
    } else if (tid < EPS0_N + EPS1_N) {
        int idx = tid - EPS0_N;
        uint2 k = tf2x32(0u, 42u, 0u, 1u);         // split(key(42))[1]
        uint2 r = tf2x32(k.x, k.y, 0u, (uint32_t)idx);
        float eps = jax_normal_bits(r.x ^ r.y);
        int j = idx / M1;
        float mean = ms[LEN_M + j];
        float var  = fabsf(ms[2 * LEN_M + M_PRI + j]) + 1e-6f;
        g_W1[idx] = fmaf(eps, sqrtf(var), mean);
    } else if (tid < EPS0_N + EPS1_N + TAIL_N) {
        int o = tid - (EPS0_N + EPS1_N);
        float v;
        if (o < LEN_M)               v = ms[o];
        else if (o < 2 * LEN_M)      v = fabsf(ms[LEN_M + M_PRI + (o - LEN_M)]) + 1e-6f;
        else if (o < 2 * LEN_M + M_PRI) v = ms[LEN_M + (o - 2 * LEN_M)];
        else                         v = fabsf(ms[2 * LEN_M + M_PRI + (o - 2 * LEN_M - M_PRI)]) + 1e-6f;
        out[tail_base + o] = v;
    }
}

// ---------------------------------------------------------------------------
// Packed f32x2 helpers (FFMA2 path, sm_103a)
// ---------------------------------------------------------------------------
typedef unsigned long long u64;

__device__ __forceinline__ u64 pk2(float a, float b) {
    u64 r;
    asm("mov.b64 %0, {%1, %2};" : "=l"(r) : "f"(a), "f"(b));
    return r;
}
__device__ __forceinline__ void upk2(u64 v, float& a, float& b) {
    asm("mov.b64 {%0, %1}, %2;" : "=f"(a), "=f"(b) : "l"(v));
}
__device__ __forceinline__ u64 fma2(u64 a, u64 b, u64 c) {
    u64 d;
    asm("fma.rn.f32x2 %0, %1, %2, %3;" : "=l"(d) : "l"(a), "l"(b), "l"(c));
    return d;
}

// ---------------------------------------------------------------------------
// Main kernel: block = (m, 128-row n-tile), 128 threads, dynamic smem.
// Phase A: outer-product layer-1: thread tile 8h x 8n, x transposed in smem.
// Phase B: thread tile 8n x 14c: 56 FFMA2 per thread-h vs 6 LDS -> FMA-bound.
// ---------------------------------------------------------------------------
__global__ void __launch_bounds__(128, 2)
pred_kernel(const float* __restrict__ x, float* __restrict__ out) {
    extern __shared__ __align__(16) float smem[];
    float* sW1p = smem + OFF_W1P;  // [j][cg][16], 14 used per group
    float* sZ   = smem + OFF_Z;    // [h][nloc(n)], stride ZS
    float* sW0  = smem + OFF_W0;   // [d*64 + h]
    float* sXP  = smem + OFF_XP;   // [d][nloc(n)], stride XS

    const int tid   = threadIdx.x;
    const int m     = blockIdx.y;
    const int nbase = blockIdx.x * NT;

    // ---- fill sW1p (8 groups of 14 c, padded to 16) ----
    for (int i = tid; i < M_PRI * W1R; i += 128) {
        int j   = i >> 7;          // / 128
        int r   = i & 127;
        int cgi = r >> 4;
        int ci  = r & 15;
        int c   = cgi * 14 + ci;
        sW1p[i] = (ci < 14 && c < M1) ? g_W1[j * M1 + c] : 0.0f;
    }
    // ---- fill sW0 ----
    for (int i = tid; i < LEN_M; i += 128)
        sW0[i] = g_W0t[m * LEN_M + i];
    // ---- fill sXP: transpose x[n][d] -> sXP[d][nloc(n)] ----
    for (int i = tid; i < NT * DDIM; i += 128) {
        int n_l = i / DDIM;
        int d   = i - n_l * DDIM;
        sXP[d * XS + nloc(n_l)] = x[(size_t)(nbase + n_l) * DDIM + d];
    }
    __syncthreads();

    // ================= Phase A: Z = relu(x . W0), 8h x 8n tile =============
    {
        const int ngr = tid & 15;          // 16 groups x 8 n
        const int hgr = tid >> 4;          // 8 groups x 8 h
        const int n0  = ngr * 8;
        const int h0  = hgr * 8;
        const int nsw = nloc(n0);

        u64 za[8][4];
#pragma unroll
        for (int i = 0; i < 8; ++i)
#pragma unroll
            for (int j = 0; j < 4; ++j) za[i][j] = 0ull;

#pragma unroll 1
        for (int d = 0; d < DDIM; ++d) {
            const float* w0p = sW0 + d * D_H + h0;
            float4 wv0 = *reinterpret_cast<const float4*>(w0p);
            float4 wv1 = *reinterpret_cast<const float4*>(w0p + 4);
            u64 ws[8];
            ws[0] = pk2(wv0.x, wv0.x); ws[1] = pk2(wv0.y, wv0.y);
            ws[2] = pk2(wv0.z, wv0.z); ws[3] = pk2(wv0.w, wv0.w);
            ws[4] = pk2(wv1.x, wv1.x); ws[5] = pk2(wv1.y, wv1.y);
            ws[6] = pk2(wv1.z, wv1.z); ws[7] = pk2(wv1.w, wv1.w);

            const float* xp = sXP + d * XS + nsw;
            ulonglong2 xq0 = *reinterpret_cast<const ulonglong2*>(xp);
            ulonglong2 xq1 = *reinterpret_cast<const ulonglong2*>(xp + 4);
            u64 xq[4] = { xq0.x, xq0.y, xq1.x, xq1.y };

#pragma unroll
            for (int i = 0; i < 8; ++i)
#pragma unroll
                for (int j = 0; j < 4; ++j)
                    za[i][j] = fma2(ws[i], xq[j], za[i][j]);
        }

        // relu + store to sZ
#pragma unroll
        for (int i = 0; i < 8; ++i) {
            float* zr = sZ + (h0 + i) * ZS + nsw;
#pragma unroll
            for (int j = 0; j < 4; ++j) {
                float a, b;
                upk2(za[i][j], a, b);
                *reinterpret_cast<u64*>(zr + 2 * j) =
                    pk2(fmaxf(a, 0.0f), fmaxf(b, 0.0f));
            }
        }
    }
    __syncthreads();

    // ================= Phase B: pred = [1;Z] . W1, 8n x 14c tile ===========
    const int ngr = tid & 15;              // 16 groups x 8 n
    const int cgr = tid >> 4;              // 8 groups x 14 c
    const int n0  = ngr * 8;
    const int nsw = nloc(n0);
    const float* w1g  = sW1p + cgr * 16;
    const float* zrow = sZ + nsw;

    u64 acc[8][7];
    {
        const float* br = w1g;             // bias row W1[0]
        ulonglong2 b0 = *reinterpret_cast<const ulonglong2*>(br);
        ulonglong2 b1 = *reinterpret_cast<const ulonglong2*>(br + 4);
        ulonglong2 b2 = *reinterpret_cast<const ulonglong2*>(br + 8);
        u64        b3 = *reinterpret_cast<const u64*>(br + 12);
        u64 w[7] = { b0.x, b0.y, b1.x, b1.y, b2.x, b2.y, b3 };
#pragma unroll
        for (int i = 0; i < 8; ++i)
#pragma unroll
            for (int j = 0; j < 7; ++j) acc[i][j] = w[j];
    }

#pragma unroll 2
    for (int h = 0; h < D_H; ++h) {
        const float* zp = zrow + h * ZS;
        ulonglong2 zq0 = *reinterpret_cast<const ulonglong2*>(zp);
        ulonglong2 zq1 = *reinterpret_cast<const ulonglong2*>(zp + 4);
        float z0, z1, z2, z3, z4, z5, z6, z7;
        upk2(zq0.x, z0, z1); upk2(zq0.y, z2, z3);
        upk2(zq1.x, z4, z5); upk2(zq1.y, z6, z7);
        u64 zs[8];
        zs[0] = pk2(z0, z0); zs[1] = pk2(z1, z1);
        zs[2] = pk2(z2, z2); zs[3] = pk2(z3, z3);
        zs[4] = pk2(z4, z4); zs[5] = pk2(z5, z5);
        zs[6] = pk2(z6, z6); zs[7] = pk2(z7, z7);

        const float* wr = w1g + (h + 1) * W1R;
        ulonglong2 w0 = *reinterpret_cast<const ulonglong2*>(wr);
        ulonglong2 w1 = *reinterpret_cast<const ulonglong2*>(wr + 4);
        ulonglong2 w2 = *reinterpret_cast<const ulonglong2*>(wr + 8);
        u64        w3 = *reinterpret_cast<const u64*>(wr + 12);
        u64 w[7] = { w0.x, w0.y, w1.x, w1.y, w2.x, w2.y, w3 };

#pragma unroll
        for (int i = 0; i < 8; ++i)
#pragma unroll
            for (int j = 0; j < 7; ++j)
                acc[i][j] = fma2(zs[i], w[j], acc[i][j]);
    }

    // ---- store: out[n][m][c], c-group cgr covers c = cgr*14 .. +13 ----
    const int coff = cgr * 14;
    const int jmax = (cgr == 7) ? 1 : 7;   // cgr 7: only c 98,99 valid
#pragma unroll
    for (int i = 0; i < 8; ++i) {
        float* o = out + ((size_t)(nbase + n0 + i) * M0 + m) * M1 + coff;
#pragma unroll
        for (int j = 0; j < 7; ++j) {
            if (j < jmax)
                *reinterpret_cast<u64*>(o + 2 * j) = acc[i][j];
        }
    }
}

// ---------------------------------------------------------------------------
// kernel_launch
// ---------------------------------------------------------------------------
extern "C" void kernel_launch(void* const* d_in, const int* in_sizes, int n_in,
                              void* d_out, int out_size) {
    const float* x  = (const float*)d_in[0];
    const float* ms = (const float*)d_in[1];
    if (n_in >= 2 && in_sizes[0] == TAIL_N) {   // defensive input id by size
        ms = (const float*)d_in[0];
        x  = (const float*)d_in[1];
    }
    float* out = (float*)d_out;
    size_t tail_base = (size_t)out_size - TAIL_N;

    static int smem_set = 0;
    const int smem_bytes = SMEM_FLOATS * sizeof(float);
    if (!smem_set) {
        cudaFuncSetAttribute(pred_kernel,
                             cudaFuncAttributeMaxDynamicSharedMemorySize,
                             smem_bytes);
        smem_set = 1;
    }

    {
        int total = EPS0_N + EPS1_N + TAIL_N;
        gen_kernel<<<(total + 255) / 256, 256>>>(ms, out, tail_base);
    }
    {
        dim3 grid(NROWS / NT, M0);
        pred_kernel<<<grid, 128, smem_bytes>>>(x, out);
    }
}

// round 11
// speedup vs baseline: 1.1020x; 1.0280x over previous
#include <cuda_runtime.h>
#include <cstdint>

// ---------------------------------------------------------------------------
// Problem constants
// ---------------------------------------------------------------------------
#define LEN_M   1088
#define D_H     64
#define M_PRI   65          // D_H + 1
#define M0      100
#define M1      100
#define NROWS   16384
#define DDIM    17          // DATA_DIM + 1
#define EPS0_N  (LEN_M * M0)            // 108800
#define EPS1_N  (M_PRI * M1)            // 6500
#define TAIL_N  (2*LEN_M + 2*M_PRI)     // 2306

#define NT      128         // n-tile per block
#define ZS      144         // sZ row stride (floats): 4 blocks x 36
#define XS      144         // sXP row stride (floats)
#define W1R     128         // padded W1 row: 8 groups x 16 floats (14 used)

// Dynamic smem layout (floats):
#define OFF_W1P 0
#define OFF_Z   (M_PRI * W1R)             //  8320
#define OFF_W0  (OFF_Z + D_H * ZS)        // 17536
#define OFF_XP  (OFF_W0 + LEN_M)          // 18624
#define SMEM_FLOATS (OFF_XP + DDIM * XS)  // 21072 floats = 84288 B

// Injective bank-rotating layout: each 32-n block in its own 36-float region.
// loc(n) = 36*(n>>5) + (n&31). 4/8-float runs stay inside one block; block
// bases (0/144/288/432 B) rotate banks by 4 floats -> LDS.128 conflict-free.
__device__ __forceinline__ int nloc(int n) {
    return ((n >> 5) * 36) + (n & 31);
}

// Scratch: sampled weights.
__device__ float g_W0t[M0 * LEN_M];   // [m][d*64+h]
__device__ float g_W1[M_PRI * M1];    // [j][c]

// ---------------------------------------------------------------------------
// Threefry-2x32 (JAX-compatible), 20 rounds
// ---------------------------------------------------------------------------
__device__ __forceinline__ uint32_t rotl32(uint32_t v, int r) {
    return (v << r) | (v >> (32 - r));
}

__device__ __forceinline__ uint2 tf2x32(uint32_t k0, uint32_t k1,
                                        uint32_t x0, uint32_t x1) {
    uint32_t ks0 = k0, ks1 = k1, ks2 = k0 ^ k1 ^ 0x1BD11BDAu;
    x0 += ks0; x1 += ks1;
#define TF_R(r) { x0 += x1; x1 = rotl32(x1, r); x1 ^= x0; }
    TF_R(13) TF_R(15) TF_R(26) TF_R(6)   x0 += ks1; x1 += ks2 + 1u;
    TF_R(17) TF_R(29) TF_R(16) TF_R(24)  x0 += ks2; x1 += ks0 + 2u;
    TF_R(13) TF_R(15) TF_R(26) TF_R(6)   x0 += ks0; x1 += ks1 + 3u;
    TF_R(17) TF_R(29) TF_R(16) TF_R(24)  x0 += ks1; x1 += ks2 + 4u;
    TF_R(13) TF_R(15) TF_R(26) TF_R(6)   x0 += ks2; x1 += ks0 + 5u;
#undef TF_R
    return make_uint2(x0, x1);
}

// XLA ErfInv (single precision, Giles polynomial)
__device__ __forceinline__ float erfinv_xla(float x) {
    float w = -log1pf(-x * x);
    float p;
    if (w < 5.0f) {
        w -= 2.5f;
        p = 2.81022636e-08f;
        p = fmaf(p, w, 3.43273939e-07f);
        p = fmaf(p, w, -3.5233877e-06f);
        p = fmaf(p, w, -4.39150654e-06f);
        p = fmaf(p, w, 0.00021858087f);
        p = fmaf(p, w, -0.00125372503f);
        p = fmaf(p, w, -0.00417768164f);
        p = fmaf(p, w, 0.246640727f);
        p = fmaf(p, w, 1.50140941f);
    } else {
        w = sqrtf(w) - 3.0f;
        p = -0.000200214257f;
        p = fmaf(p, w, 0.000100950558f);
        p = fmaf(p, w, 0.00134934322f);
        p = fmaf(p, w, -0.00367342844f);
        p = fmaf(p, w, 0.00573950773f);
        p = fmaf(p, w, -0.0076224613f);
        p = fmaf(p, w, 0.00943887047f);
        p = fmaf(p, w, 1.00167406f);
        p = fmaf(p, w, 2.83297682f);
    }
    return p * x;
}

// JAX random.normal(key, ..., f32), partitionable path
__device__ __forceinline__ float jax_normal_bits(uint32_t bits) {
    const float LO = __uint_as_float(0xBF7FFFFFu);      // nextafter(-1, 0)
    float f = __uint_as_float((bits >> 9) | 0x3F800000u) - 1.0f;  // [0,1)
    float u = f * 2.0f + LO;
    u = fmaxf(u, LO);
    return 1.41421356237309515f * erfinv_xla(u);
}

// ---------------------------------------------------------------------------
// Gen kernel: sample W0 (transposed per-m), W1, and write tail outputs
// ---------------------------------------------------------------------------
__global__ void gen_kernel(const float* __restrict__ ms, float* __restrict__ out,
                           size_t tail_base) {
    int tid = blockIdx.x * blockDim.x + threadIdx.x;
    if (tid < EPS0_N) {
        uint2 k = tf2x32(0u, 42u, 0u, 0u);         // split(key(42))[0]
        uint2 r = tf2x32(k.x, k.y, 0u, (uint32_t)tid);
        float eps = jax_normal_bits(r.x ^ r.y);
        int i = tid / M0;
        int m = tid - i * M0;
        float mean = ms[i];
        float var  = fabsf(ms[LEN_M + M_PRI + i]) + 1e-6f;
        g_W0t[m * LEN_M + i] = fmaf(eps, sqrtf(var), mean);
    } else if (tid < EPS0_N + EPS1_N) {
        int idx = tid - EPS0_N;
        uint2 k = tf2x32(0u, 42u, 0u, 1u);         // split(key(42))[1]
        uint2 r = tf2x32(k.x, k.y, 0u, (uint32_t)idx);
        float eps = jax_normal_bits(r.x ^ r.y);
        int j = idx / M1;
        float mean = ms[LEN_M + j];
        float var  = fabsf(ms[2 * LEN_M + M_PRI + j]) + 1e-6f;
        g_W1[idx] = fmaf(eps, sqrtf(var), mean);
    } else if (tid < EPS0_N + EPS1_N + TAIL_N) {
        int o = tid - (EPS0_N + EPS1_N);
        float v;
        if (o < LEN_M)               v = ms[o];
        else if (o < 2 * LEN_M)      v = fabsf(ms[LEN_M + M_PRI + (o - LEN_M)]) + 1e-6f;
        else if (o < 2 * LEN_M + M_PRI) v = ms[LEN_M + (o - 2 * LEN_M)];
        else                         v = fabsf(ms[2 * LEN_M + M_PRI + (o - 2 * LEN_M - M_PRI)]) + 1e-6f;
        out[tail_base + o] = v;
    }
}

// ---------------------------------------------------------------------------
// Packed f32x2 helpers (FFMA2 path, sm_103a)
// ---------------------------------------------------------------------------
typedef unsigned long long u64;

__device__ __forceinline__ u64 pk2(float a, float b) {
    u64 r;
    asm("mov.b64 %0, {%1, %2};" : "=l"(r) : "f"(a), "f"(b));
    return r;
}
__device__ __forceinline__ void upk2(u64 v, float& a, float& b) {
    asm("mov.b64 {%0, %1}, %2;" : "=f"(a), "=f"(b) : "l"(v));
}
__device__ __forceinline__ u64 fma2(u64 a, u64 b, u64 c) {
    u64 d;
    asm("fma.rn.f32x2 %0, %1, %2, %3;" : "=l"(d) : "l"(a), "l"(b), "l"(c));
    return d;
}

// ---------------------------------------------------------------------------
// Main kernel: block = (m, 128-row n-tile), 256 threads, dynamic smem.
// 16 warps/SM (2 blocks) = 4 warps/SMSP for latency hiding.
// Phase A: thread tile 4h x 8n (outer product, x transposed in smem).
// Phase B: thread tile 4n x 14c (28 FFMA2 vs 5 LDS per thread-h).
// ---------------------------------------------------------------------------
__global__ void __launch_bounds__(256, 2)
pred_kernel(const float* __restrict__ x, float* __restrict__ out) {
    extern __shared__ __align__(16) float smem[];
    float* sW1p = smem + OFF_W1P;  // [j][cg][16], 14 used per group
    float* sZ   = smem + OFF_Z;    // [h][nloc(n)], stride ZS
    float* sW0  = smem + OFF_W0;   // [d*64 + h]
    float* sXP  = smem + OFF_XP;   // [d][nloc(n)], stride XS

    const int tid   = threadIdx.x;
    const int m     = blockIdx.y;
    const int nbase = blockIdx.x * NT;

    // ---- fill sW1p (8 groups of 14 c, padded to 16) ----
    for (int i = tid; i < M_PRI * W1R; i += 256) {
        int j   = i >> 7;          // / 128
        int r   = i & 127;
        int cgi = r >> 4;
        int ci  = r & 15;
        int c   = cgi * 14 + ci;
        sW1p[i] = (ci < 14 && c < M1) ? g_W1[j * M1 + c] : 0.0f;
    }
    // ---- fill sW0 ----
    for (int i = tid; i < LEN_M; i += 256)
        sW0[i] = g_W0t[m * LEN_M + i];
    // ---- fill sXP: transpose x[n][d] -> sXP[d][nloc(n)] ----
    for (int i = tid; i < NT * DDIM; i += 256) {
        int n_l = i / DDIM;
        int d   = i - n_l * DDIM;
        sXP[d * XS + nloc(n_l)] = x[(size_t)(nbase + n_l) * DDIM + d];
    }
    __syncthreads();

    // ================= Phase A: Z = relu(x . W0), 4h x 8n tile =============
    {
        const int ngr = tid & 15;          // 16 groups x 8 n
        const int hgr = tid >> 4;          // 16 groups x 4 h
        const int n0  = ngr * 8;
        const int h0  = hgr * 4;
        const int nsw = nloc(n0);

        u64 za[4][4];
#pragma unroll
        for (int i = 0; i < 4; ++i)
#pragma unroll
            for (int j = 0; j < 4; ++j) za[i][j] = 0ull;

#pragma unroll 1
        for (int d = 0; d < DDIM; ++d) {
            float4 wv = *reinterpret_cast<const float4*>(sW0 + d * D_H + h0);
            u64 ws[4];
            ws[0] = pk2(wv.x, wv.x); ws[1] = pk2(wv.y, wv.y);
            ws[2] = pk2(wv.z, wv.z); ws[3] = pk2(wv.w, wv.w);

            const float* xp = sXP + d * XS + nsw;
            ulonglong2 xq0 = *reinterpret_cast<const ulonglong2*>(xp);
            ulonglong2 xq1 = *reinterpret_cast<const ulonglong2*>(xp + 4);
            u64 xq[4] = { xq0.x, xq0.y, xq1.x, xq1.y };

#pragma unroll
            for (int i = 0; i < 4; ++i)
#pragma unroll
                for (int j = 0; j < 4; ++j)
                    za[i][j] = fma2(ws[i], xq[j], za[i][j]);
        }

        // relu + store to sZ
#pragma unroll
        for (int i = 0; i < 4; ++i) {
            float* zr = sZ + (h0 + i) * ZS + nsw;
#pragma unroll
            for (int j = 0; j < 4; ++j) {
                float a, b;
                upk2(za[i][j], a, b);
                *reinterpret_cast<u64*>(zr + 2 * j) =
                    pk2(fmaxf(a, 0.0f), fmaxf(b, 0.0f));
            }
        }
    }
    __syncthreads();

    // ================= Phase B: pred = [1;Z] . W1, 4n x 14c tile ===========
    const int ngr = tid & 31;              // 32 groups x 4 n
    const int cgr = tid >> 5;              // 8 warps: uniform c-group per warp
    const int n0  = ngr * 4;
    const int nsw = nloc(n0);
    const float* w1g  = sW1p + cgr * 16;
    const float* zrow = sZ + nsw;

    u64 acc[4][7];
    {
        const float* br = w1g;             // bias row W1[0]
        ulonglong2 b0 = *reinterpret_cast<const ulonglong2*>(br);
        ulonglong2 b1 = *reinterpret_cast<const ulonglong2*>(br + 4);
        ulonglong2 b2 = *reinterpret_cast<const ulonglong2*>(br + 8);
        u64        b3 = *reinterpret_cast<const u64*>(br + 12);
        u64 w[7] = { b0.x, b0.y, b1.x, b1.y, b2.x, b2.y, b3 };
#pragma unroll
        for (int i = 0; i < 4; ++i)
#pragma unroll
            for (int j = 0; j < 7; ++j) acc[i][j] = w[j];
    }

#pragma unroll 4
    for (int h = 0; h < D_H; ++h) {
        ulonglong2 zq = *reinterpret_cast<const ulonglong2*>(zrow + h * ZS);
        float z0, z1, z2, z3;
        upk2(zq.x, z0, z1); upk2(zq.y, z2, z3);
        u64 zs[4];
        zs[0] = pk2(z0, z0); zs[1] = pk2(z1, z1);
        zs[2] = pk2(z2, z2); zs[3] = pk2(z3, z3);

        const float* wr = w1g + (h + 1) * W1R;
        ulonglong2 w0 = *reinterpret_cast<const ulonglong2*>(wr);
        ulonglong2 w1 = *reinterpret_cast<const ulonglong2*>(wr + 4);
        ulonglong2 w2 = *reinterpret_cast<const ulonglong2*>(wr + 8);
        u64        w3 = *reinterpret_cast<const u64*>(wr + 12);
        u64 w[7] = { w0.x, w0.y, w1.x, w1.y, w2.x, w2.y, w3 };

#pragma unroll
        for (int i = 0; i < 4; ++i)
#pragma unroll
            for (int j = 0; j < 7; ++j)
                acc[i][j] = fma2(zs[i], w[j], acc[i][j]);
    }

    // ---- store: out[n][m][c], c-group cgr covers c = cgr*14 .. +13 ----
    const int coff = cgr * 14;
    const int jmax = (cgr == 7) ? 1 : 7;   // cgr 7: only c 98,99 valid
#pragma unroll
    for (int i = 0; i < 4; ++i) {
        float* o = out + ((size_t)(nbase + n0 + i) * M0 + m) * M1 + coff;
#pragma unroll
        for (int j = 0; j < 7; ++j) {
            if (j < jmax)
                *reinterpret_cast<u64*>(o + 2 * j) = acc[i][j];
        }
    }
}

// ---------------------------------------------------------------------------
// kernel_launch
// ---------------------------------------------------------------------------
extern "C" void kernel_launch(void* const* d_in, const int* in_sizes, int n_in,
                              void* d_out, int out_size) {
    const float* x  = (const float*)d_in[0];
    const float* ms = (const float*)d_in[1];
    if (n_in >= 2 && in_sizes[0] == TAIL_N) {   // defensive input id by size
        ms = (const float*)d_in[0];
        x  = (const float*)d_in[1];
    }
    float* out = (float*)d_out;
    size_t tail_base = (size_t)out_size - TAIL_N;

    static int smem_set = 0;
    const int smem_bytes = SMEM_FLOATS * sizeof(float);
    if (!smem_set) {
        cudaFuncSetAttribute(pred_kernel,
                             cudaFuncAttributeMaxDynamicSharedMemorySize,
                             smem_bytes);
        smem_set = 1;
    }

    {
        int total = EPS0_N + EPS1_N + TAIL_N;
        gen_kernel<<<(total + 255) / 256, 256>>>(ms, out, tail_base);
    }
    {
        dim3 grid(NROWS / NT, M0);
        pred_kernel<<<grid, 256, smem_bytes>>>(x, out);
    }
}

// round 13
// speedup vs baseline: 1.8487x; 1.6775x over previous
#include <cuda_runtime.h>
#include <cuda_bf16.h>
#include <cstdint>

// ---------------------------------------------------------------------------
// Problem constants
// ---------------------------------------------------------------------------
#define LEN_M   1088
#define D_H     64
#define M_PRI   65          // D_H + 1
#define M0      100
#define M1      100
#define NROWS   16384
#define DDIM    17          // DATA_DIM + 1
#define EPS0_N  (LEN_M * M0)            // 108800
#define TAIL_N  (2*LEN_M + 2*M_PRI)     // 2306

#define NT      128         // n-tile per block (MMA M = 8 warps x 16)
#define XS      144         // sXP row stride (floats), injective block layout
#define NC      104         // padded c (13 x 8)
#define KP      80          // padded K: k 0..63 = h, k 64 = bias, 65..79 = 0
#define KS2     88          // row stride in bf16 (176 B, conflict-free)
#define ZB      176         // row stride bytes
#define BFILL_N (NC * KS2)  // 9152

// Dynamic smem layout (floats):
#define OFF_W0  0
#define OFF_XP  1088
#define OFF_ZH  3536                        // 14144 B (16B aligned)
#define OFF_ZL  (OFF_ZH + NT * ZB / 4)      // 9168
#define OFF_BH  (OFF_ZL + NT * ZB / 4)      // 14800
#define OFF_BL  (OFF_BH + NC * ZB / 4)      // 19376
#define SMEM_FLOATS (OFF_BL + NC * ZB / 4)  // 23952 floats = 95808 B

// injective padded-block layout for sXP columns
__device__ __forceinline__ int nloc(int n) { return ((n >> 5) * 36) + (n & 31); }

// Scratch
__device__ float g_W0t[M0 * LEN_M];                 // [m][d*64+h]
__device__ __nv_bfloat16 g_Bh[NC * KS2];            // W1 hi, [c][k]
__device__ __nv_bfloat16 g_Bl[NC * KS2];            // W1 lo, [c][k]

// ---------------------------------------------------------------------------
// Threefry-2x32 (JAX-compatible), 20 rounds
// ---------------------------------------------------------------------------
__device__ __forceinline__ uint32_t rotl32(uint32_t v, int r) {
    return (v << r) | (v >> (32 - r));
}
__device__ __forceinline__ uint2 tf2x32(uint32_t k0, uint32_t k1,
                                        uint32_t x0, uint32_t x1) {
    uint32_t ks0 = k0, ks1 = k1, ks2 = k0 ^ k1 ^ 0x1BD11BDAu;
    x0 += ks0; x1 += ks1;
#define TF_R(r) { x0 += x1; x1 = rotl32(x1, r); x1 ^= x0; }
    TF_R(13) TF_R(15) TF_R(26) TF_R(6)   x0 += ks1; x1 += ks2 + 1u;
    TF_R(17) TF_R(29) TF_R(16) TF_R(24)  x0 += ks2; x1 += ks0 + 2u;
    TF_R(13) TF_R(15) TF_R(26) TF_R(6)   x0 += ks0; x1 += ks1 + 3u;
    TF_R(17) TF_R(29) TF_R(16) TF_R(24)  x0 += ks1; x1 += ks2 + 4u;
    TF_R(13) TF_R(15) TF_R(26) TF_R(6)   x0 += ks2; x1 += ks0 + 5u;
#undef TF_R
    return make_uint2(x0, x1);
}
__device__ __forceinline__ float erfinv_xla(float x) {
    float w = -log1pf(-x * x);
    float p;
    if (w < 5.0f) {
        w -= 2.5f;
        p = 2.81022636e-08f;
        p = fmaf(p, w, 3.43273939e-07f);
        p = fmaf(p, w, -3.5233877e-06f);
        p = fmaf(p, w, -4.39150654e-06f);
        p = fmaf(p, w, 0.00021858087f);
        p = fmaf(p, w, -0.00125372503f);
        p = fmaf(p, w, -0.00417768164f);
        p = fmaf(p, w, 0.246640727f);
        p = fmaf(p, w, 1.50140941f);
    } else {
        w = sqrtf(w) - 3.0f;
        p = -0.000200214257f;
        p = fmaf(p, w, 0.000100950558f);
        p = fmaf(p, w, 0.00134934322f);
        p = fmaf(p, w, -0.00367342844f);
        p = fmaf(p, w, 0.00573950773f);
        p = fmaf(p, w, -0.0076224613f);
        p = fmaf(p, w, 0.00943887047f);
        p = fmaf(p, w, 1.00167406f);
        p = fmaf(p, w, 2.83297682f);
    }
    return p * x;
}
__device__ __forceinline__ float jax_normal_bits(uint32_t bits) {
    const float LO = __uint_as_float(0xBF7FFFFFu);
    float f = __uint_as_float((bits >> 9) | 0x3F800000u) - 1.0f;
    float u = f * 2.0f + LO;
    u = fmaxf(u, LO);
    return 1.41421356237309515f * erfinv_xla(u);
}
__device__ __forceinline__ float w1_sample(const float* ms, int j, int c) {
    uint2 k = tf2x32(0u, 42u, 0u, 1u);            // split(key(42))[1]
    uint2 r = tf2x32(k.x, k.y, 0u, (uint32_t)(j * M1 + c));
    float eps = jax_normal_bits(r.x ^ r.y);
    float mean = ms[LEN_M + j];
    float var  = fabsf(ms[2 * LEN_M + M_PRI + j]) + 1e-6f;
    return fmaf(eps, sqrtf(var), mean);
}

// ---------------------------------------------------------------------------
// Gen kernel: W0t samples, W1 hi/lo B arrays [c][k], tail outputs
// ---------------------------------------------------------------------------
__global__ void gen_kernel(const float* __restrict__ ms, float* __restrict__ out,
                           size_t tail_base) {
    int tid = blockIdx.x * blockDim.x + threadIdx.x;
    if (tid < EPS0_N) {
        uint2 k = tf2x32(0u, 42u, 0u, 0u);        // split(key(42))[0]
        uint2 r = tf2x32(k.x, k.y, 0u, (uint32_t)tid);
        float eps = jax_normal_bits(r.x ^ r.y);
        int i = tid / M0;
        int m = tid - i * M0;
        float mean = ms[i];
        float var  = fabsf(ms[LEN_M + M_PRI + i]) + 1e-6f;
        g_W0t[m * LEN_M + i] = fmaf(eps, sqrtf(var), mean);
    } else if (tid < EPS0_N + BFILL_N) {
        int o = tid - EPS0_N;
        int c = o / KS2;        // 0..103
        int k = o - c * KS2;    // 0..87
        float v = 0.0f;
        if (c < M1) {
            if (k < 64)       v = w1_sample(ms, k + 1, c);
            else if (k == 64) v = w1_sample(ms, 0, c);
        }
        __nv_bfloat16 hi = __float2bfloat16(v);
        __nv_bfloat16 lo = __float2bfloat16(v - __bfloat162float(hi));
        g_Bh[c * KS2 + k] = hi;
        g_Bl[c * KS2 + k] = lo;
    } else if (tid < EPS0_N + BFILL_N + TAIL_N) {
        int o = tid - (EPS0_N + BFILL_N);
        float v;
        if (o < LEN_M)               v = ms[o];
        else if (o < 2 * LEN_M)      v = fabsf(ms[LEN_M + M_PRI + (o - LEN_M)]) + 1e-6f;
        else if (o < 2 * LEN_M + M_PRI) v = ms[LEN_M + (o - 2 * LEN_M)];
        else                         v = fabsf(ms[2 * LEN_M + M_PRI + (o - 2 * LEN_M - M_PRI)]) + 1e-6f;
        out[tail_base + o] = v;
    }
}

// ---------------------------------------------------------------------------
// f32x2 helpers (phase A)
// ---------------------------------------------------------------------------
typedef unsigned long long u64;
__device__ __forceinline__ u64 pk2(float a, float b) {
    u64 r; asm("mov.b64 %0, {%1, %2};" : "=l"(r) : "f"(a), "f"(b)); return r;
}
__device__ __forceinline__ void upk2(u64 v, float& a, float& b) {
    asm("mov.b64 {%0, %1}, %2;" : "=f"(a), "=f"(b) : "l"(v));
}
__device__ __forceinline__ u64 fma2(u64 a, u64 b, u64 c) {
    u64 d; asm("fma.rn.f32x2 %0, %1, %2, %3;" : "=l"(d) : "l"(a), "l"(b), "l"(c));
    return d;
}

// mma.sync m16n8k16 bf16 -> f32 accumulate (base PTX, sm_80+)
__device__ __forceinline__ void mma_bf16(float* c, const uint32_t* a,
                                         const uint32_t* b) {
    asm volatile(
        "mma.sync.aligned.m16n8k16.row.col.f32.bf16.bf16.f32 "
        "{%0,%1,%2,%3}, {%4,%5,%6,%7}, {%8,%9}, {%0,%1,%2,%3};"
        : "+f"(c[0]), "+f"(c[1]), "+f"(c[2]), "+f"(c[3])
        : "r"(a[0]), "r"(a[1]), "r"(a[2]), "r"(a[3]), "r"(b[0]), "r"(b[1]));
}

// ---------------------------------------------------------------------------
// Main kernel: block = (m, 128-n tile), 256 threads (8 warps).
// Phase A (FFMA2): z = relu(x.W0) -> bf16 hi/lo into [n][k] smem tiles.
// Phase B (HMMA): each warp D[16n x 104c] = Z.W1^T, 13 tiles x 5 ksteps x
//                 3 split-mma (hh, hl, lh) into shared f32 accumulators.
// ---------------------------------------------------------------------------
__global__ void __launch_bounds__(256, 2)
pred_kernel(const float* __restrict__ x, float* __restrict__ out) {
    extern __shared__ __align__(16) float smem[];
    float* sW0 = smem + OFF_W0;
    float* sXP = smem + OFF_XP;
    char*  sZh = reinterpret_cast<char*>(smem + OFF_ZH);
    char*  sZl = reinterpret_cast<char*>(smem + OFF_ZL);
    char*  sBh = reinterpret_cast<char*>(smem + OFF_BH);
    char*  sBl = reinterpret_cast<char*>(smem + OFF_BL);

    const int tid   = threadIdx.x;
    const int wid   = tid >> 5;
    const int lid   = tid & 31;
    const int m     = blockIdx.y;
    const int nbase = blockIdx.x * NT;

    // ---- fills ----
    for (int i = tid; i < LEN_M; i += 256)
        sW0[i] = g_W0t[m * LEN_M + i];
    for (int i = tid; i < NT * DDIM; i += 256) {
        int n_l = i / DDIM;
        int d   = i - n_l * DDIM;
        sXP[d * XS + nloc(n_l)] = x[(size_t)(nbase + n_l) * DDIM + d];
    }
    {
        const float4* gh = reinterpret_cast<const float4*>(g_Bh);
        const float4* gl = reinterpret_cast<const float4*>(g_Bl);
        float4* bh = reinterpret_cast<float4*>(sBh);
        float4* bl = reinterpret_cast<float4*>(sBl);
        for (int i = tid; i < NC * ZB / 16; i += 256) {
            bh[i] = gh[i];
            bl[i] = gl[i];
        }
    }
    if (tid < NT) {
        // zero k = 64..87 (48 B) in both Z tiles, then bias hi at k = 64
        char* ph = sZh + tid * ZB + 128;
        char* pl = sZl + tid * ZB + 128;
        uint4 z4 = make_uint4(0, 0, 0, 0);
        *reinterpret_cast<uint4*>(ph)      = z4;
        *reinterpret_cast<uint4*>(ph + 16) = z4;
        *reinterpret_cast<uint4*>(ph + 32) = z4;
        *reinterpret_cast<uint4*>(pl)      = z4;
        *reinterpret_cast<uint4*>(pl + 16) = z4;
        *reinterpret_cast<uint4*>(pl + 32) = z4;
        *reinterpret_cast<unsigned short*>(ph) = 0x3F80;  // bf16 1.0 at k=64
    }
    __syncthreads();

    // ================= Phase A: 4h x 8n per thread (R11-proven) ===========
    {
        const int ngr = tid & 15;          // 16 groups x 8 n
        const int hgr = tid >> 4;          // 16 groups x 4 h
        const int n0  = ngr * 8;
        const int h0  = hgr * 4;
        const int nsw = nloc(n0);

        u64 za[4][4];
#pragma unroll
        for (int i = 0; i < 4; ++i)
#pragma unroll
            for (int j = 0; j < 4; ++j) za[i][j] = 0ull;

#pragma unroll 1
        for (int d = 0; d < DDIM; ++d) {
            float4 wv = *reinterpret_cast<const float4*>(sW0 + d * D_H + h0);
            u64 ws[4];
            ws[0] = pk2(wv.x, wv.x); ws[1] = pk2(wv.y, wv.y);
            ws[2] = pk2(wv.z, wv.z); ws[3] = pk2(wv.w, wv.w);
            const float* xp = sXP + d * XS + nsw;
            ulonglong2 xq0 = *reinterpret_cast<const ulonglong2*>(xp);
            ulonglong2 xq1 = *reinterpret_cast<const ulonglong2*>(xp + 4);
            u64 xq[4] = { xq0.x, xq0.y, xq1.x, xq1.y };
#pragma unroll
            for (int i = 0; i < 4; ++i)
#pragma unroll
                for (int j = 0; j < 4; ++j)
                    za[i][j] = fma2(ws[i], xq[j], za[i][j]);
        }

        // relu + bf16 split, store transposed: sZ[n][k=h0..h0+3] (8B each)
#pragma unroll
        for (int j = 0; j < 4; ++j) {
            float ev[4], ov[4];
#pragma unroll
            for (int i = 0; i < 4; ++i) upk2(za[i][j], ev[i], ov[i]);
            u64 he = 0, le = 0, ho = 0, lo = 0;
#pragma unroll
            for (int i = 0; i < 4; ++i) {
                float ve = fmaxf(ev[i], 0.0f);
                float vo = fmaxf(ov[i], 0.0f);
                __nv_bfloat16 heb = __float2bfloat16(ve);
                __nv_bfloat16 hob = __float2bfloat16(vo);
                he |= (u64)__bfloat16_as_ushort(heb) << (16 * i);
                ho |= (u64)__bfloat16_as_ushort(hob) << (16 * i);
                le |= (u64)__bfloat16_as_ushort(
                          __float2bfloat16(ve - __bfloat162float(heb))) << (16 * i);
                lo |= (u64)__bfloat16_as_ushort(
                          __float2bfloat16(vo - __bfloat162float(hob))) << (16 * i);
            }
            int ne = n0 + 2 * j, no = ne + 1;
            *reinterpret_cast<u64*>(sZh + ne * ZB + h0 * 2) = he;
            *reinterpret_cast<u64*>(sZl + ne * ZB + h0 * 2) = le;
            *reinterpret_cast<u64*>(sZh + no * ZB + h0 * 2) = ho;
            *reinterpret_cast<u64*>(sZl + no * ZB + h0 * 2) = lo;
        }
    }
    __syncthreads();

    // ================= Phase B: warp-level HMMA ===========================
    const int g  = lid >> 2;               // 0..7
    const int tg = lid & 3;                // 0..3
    const int wr = wid * 16;               // warp's row base

    float acc[13][4];
#pragma unroll
    for (int t = 0; t < 13; ++t)
#pragma unroll
        for (int q = 0; q < 4; ++q) acc[t][q] = 0.0f;

    const char* zr0 = sZh + (wr + g) * ZB;
    const char* zr1 = sZh + (wr + g + 8) * ZB;
    const char* zl0 = sZl + (wr + g) * ZB;
    const char* zl1 = sZl + (wr + g + 8) * ZB;

#pragma unroll
    for (int s = 0; s < 5; ++s) {
        const int kb = s * 32 + tg * 4;    // byte offset of k pair
        uint32_t ah[4], al[4];
        ah[0] = *reinterpret_cast<const uint32_t*>(zr0 + kb);
        ah[1] = *reinterpret_cast<const uint32_t*>(zr1 + kb);
        ah[2] = *reinterpret_cast<const uint32_t*>(zr0 + kb + 16);
        ah[3] = *reinterpret_cast<const uint32_t*>(zr1 + kb + 16);
        al[0] = *reinterpret_cast<const uint32_t*>(zl0 + kb);
        al[1] = *reinterpret_cast<const uint32_t*>(zl1 + kb);
        al[2] = *reinterpret_cast<const uint32_t*>(zl0 + kb + 16);
        al[3] = *reinterpret_cast<const uint32_t*>(zl1 + kb + 16);

#pragma unroll
        for (int t = 0; t < 13; ++t) {
            const char* bh = sBh + (t * 8 + g) * ZB + kb;
            const char* bl = sBl + (t * 8 + g) * ZB + kb;
            uint32_t bhf[2], blf[2];
            bhf[0] = *reinterpret_cast<const uint32_t*>(bh);
            bhf[1] = *reinterpret_cast<const uint32_t*>(bh + 16);
            blf[0] = *reinterpret_cast<const uint32_t*>(bl);
            blf[1] = *reinterpret_cast<const uint32_t*>(bl + 16);
            mma_bf16(acc[t], ah, bhf);     // hi * hi
            mma_bf16(acc[t], ah, blf);     // hi * lo
            mma_bf16(acc[t], al, bhf);     // lo * hi
        }
    }

    // ---- store: D rows wr+g, wr+g+8; cols t*8 + tg*2 (+1) ----
    {
        const int n0g = nbase + wr + g;
        float* o0 = out + ((size_t)n0g * M0 + m) * M1;
        float* o1 = out + ((size_t)(n0g + 8) * M0 + m) * M1;
        const int cb = tg * 2;
#pragma unroll
        for (int t = 0; t < 13; ++t) {
            int c = t * 8 + cb;
            if (c < M1) {                   // t==12: only tg<2 valid
                *reinterpret_cast<float2*>(o0 + c) = make_float2(acc[t][0], acc[t][1]);
                *reinterpret_cast<float2*>(o1 + c) = make_float2(acc[t][2], acc[t][3]);
            }
        }
    }
}

// ---------------------------------------------------------------------------
// kernel_launch
// ---------------------------------------------------------------------------
extern "C" void kernel_launch(void* const* d_in, const int* in_sizes, int n_in,
                              void* d_out, int out_size) {
    const float* x  = (const float*)d_in[0];
    const float* ms = (const float*)d_in[1];
    if (n_in >= 2 && in_sizes[0] == TAIL_N) {   // defensive input id by size
        ms = (const float*)d_in[0];
        x  = (const float*)d_in[1];
    }
    float* out = (float*)d_out;
    size_t tail_base = (size_t)out_size - TAIL_N;

    static int smem_set = 0;
    const int smem_bytes = SMEM_FLOATS * sizeof(float);
    if (!smem_set) {
        cudaFuncSetAttribute(pred_kernel,
                             cudaFuncAttributeMaxDynamicSharedMemorySize,
                             smem_bytes);
        smem_set = 1;
    }

    {
        int total = EPS0_N + BFILL_N + TAIL_N;
        gen_kernel<<<(total + 255) / 256, 256>>>(ms, out, tail_base);
    }
    {
        dim3 grid(NROWS / NT, M0);
        pred_kernel<<<grid, 256, smem_bytes>>>(x, out);
    }
}

// round 14
// speedup vs baseline: 2.4804x; 1.3417x over previous
#include <cuda_runtime.h>
#include <cuda_bf16.h>
#include <cstdint>

// ---------------------------------------------------------------------------
// Problem constants
// ---------------------------------------------------------------------------
#define LEN_M   1088
#define D_H     64
#define M_PRI   65          // D_H + 1
#define M0      100
#define M1      100
#define NROWS   16384
#define DDIM    17          // DATA_DIM + 1
#define EPS0_N  (LEN_M * M0)            // 108800
#define TAIL_N  (2*LEN_M + 2*M_PRI)     // 2306

#define NT      128         // n-tile per block
#define XS      144         // sXP row stride (floats), injective block layout
#define NTI     13          // c tiles (8 wide) -> 104 padded
#define NS      5           // k steps (K = 80: 64 h + bias@64 + zeros)

// A fragments: 8 wb (16-row blocks) x 5 s x 32 lanes x 4 regs, wb stride padded
#define AWBS    644                     // 5*32*4 + 4 (bank rotation)
#define AFRAG_U32 (8 * AWBS)            // 5152
// B fragments: 13 t x 5 s x 32 lanes x 2 regs
#define BFRAG_U32 (NTI * NS * 32 * 2)   // 4160
#define BTASKS    (NTI * NS * 32 * 2)   // gen tasks (one u32 pair each)

// Dynamic smem layout (floats / u32 units):
#define OFF_W0  0
#define OFF_XP  1088
#define OFF_AH  (OFF_XP + DDIM * XS)        // 3536
#define OFF_AL  (OFF_AH + AFRAG_U32)        // 8688
#define OFF_BH  (OFF_AL + AFRAG_U32)        // 13840
#define OFF_BL  (OFF_BH + BFRAG_U32)        // 18000
#define SMEM_FLOATS (OFF_BL + BFRAG_U32)    // 22160 floats = 88640 B

// injective padded-block layout for sXP columns
__device__ __forceinline__ int nloc(int n) { return ((n >> 5) * 36) + (n & 31); }

// Scratch
__device__ float g_W0t[M0 * LEN_M];          // [m][d*64+h]
__device__ uint32_t g_Bh[BFRAG_U32];         // W1 hi fragments
__device__ uint32_t g_Bl[BFRAG_U32];         // W1 lo fragments

// ---------------------------------------------------------------------------
// Threefry-2x32 (JAX-compatible), 20 rounds
// ---------------------------------------------------------------------------
__device__ __forceinline__ uint32_t rotl32(uint32_t v, int r) {
    return (v << r) | (v >> (32 - r));
}
__device__ __forceinline__ uint2 tf2x32(uint32_t k0, uint32_t k1,
                                        uint32_t x0, uint32_t x1) {
    uint32_t ks0 = k0, ks1 = k1, ks2 = k0 ^ k1 ^ 0x1BD11BDAu;
    x0 += ks0; x1 += ks1;
#define TF_R(r) { x0 += x1; x1 = rotl32(x1, r); x1 ^= x0; }
    TF_R(13) TF_R(15) TF_R(26) TF_R(6)   x0 += ks1; x1 += ks2 + 1u;
    TF_R(17) TF_R(29) TF_R(16) TF_R(24)  x0 += ks2; x1 += ks0 + 2u;
    TF_R(13) TF_R(15) TF_R(26) TF_R(6)   x0 += ks0; x1 += ks1 + 3u;
    TF_R(17) TF_R(29) TF_R(16) TF_R(24)  x0 += ks1; x1 += ks2 + 4u;
    TF_R(13) TF_R(15) TF_R(26) TF_R(6)   x0 += ks2; x1 += ks0 + 5u;
#undef TF_R
    return make_uint2(x0, x1);
}
__device__ __forceinline__ float erfinv_xla(float x) {
    float w = -log1pf(-x * x);
    float p;
    if (w < 5.0f) {
        w -= 2.5f;
        p = 2.81022636e-08f;
        p = fmaf(p, w, 3.43273939e-07f);
        p = fmaf(p, w, -3.5233877e-06f);
        p = fmaf(p, w, -4.39150654e-06f);
        p = fmaf(p, w, 0.00021858087f);
        p = fmaf(p, w, -0.00125372503f);
        p = fmaf(p, w, -0.00417768164f);
        p = fmaf(p, w, 0.246640727f);
        p = fmaf(p, w, 1.50140941f);
    } else {
        w = sqrtf(w) - 3.0f;
        p = -0.000200214257f;
        p = fmaf(p, w, 0.000100950558f);
        p = fmaf(p, w, 0.00134934322f);
        p = fmaf(p, w, -0.00367342844f);
        p = fmaf(p, w, 0.00573950773f);
        p = fmaf(p, w, -0.0076224613f);
        p = fmaf(p, w, 0.00943887047f);
        p = fmaf(p, w, 1.00167406f);
        p = fmaf(p, w, 2.83297682f);
    }
    return p * x;
}
__device__ __forceinline__ float jax_normal_bits(uint32_t bits) {
    const float LO = __uint_as_float(0xBF7FFFFFu);
    float f = __uint_as_float((bits >> 9) | 0x3F800000u) - 1.0f;
    float u = f * 2.0f + LO;
    u = fmaxf(u, LO);
    return 1.41421356237309515f * erfinv_xla(u);
}
__device__ __forceinline__ float w1_sample(const float* ms, int j, int c) {
    uint2 k = tf2x32(0u, 42u, 0u, 1u);            // split(key(42))[1]
    uint2 r = tf2x32(k.x, k.y, 0u, (uint32_t)(j * M1 + c));
    float eps = jax_normal_bits(r.x ^ r.y);
    float mean = ms[LEN_M + j];
    float var  = fabsf(ms[2 * LEN_M + M_PRI + j]) + 1e-6f;
    return fmaf(eps, sqrtf(var), mean);
}
// logical W1[k][c] with bias row at k=64, zeros beyond
__device__ __forceinline__ float w1_at(const float* ms, int k, int c) {
    if (c >= M1 || k > 64) return 0.0f;
    return (k < 64) ? w1_sample(ms, k + 1, c) : w1_sample(ms, 0, c);
}

// ---------------------------------------------------------------------------
// Gen kernel: W0t samples, B fragments (mma layout, hi/lo), tail outputs
// ---------------------------------------------------------------------------
__global__ void gen_kernel(const float* __restrict__ ms, float* __restrict__ out,
                           size_t tail_base) {
    int tid = blockIdx.x * blockDim.x + threadIdx.x;
    if (tid < EPS0_N) {
        uint2 k = tf2x32(0u, 42u, 0u, 0u);        // split(key(42))[0]
        uint2 r = tf2x32(k.x, k.y, 0u, (uint32_t)tid);
        float eps = jax_normal_bits(r.x ^ r.y);
        int i = tid / M0;
        int m = tid - i * M0;
        float mean = ms[i];
        float var  = fabsf(ms[LEN_M + M_PRI + i]) + 1e-6f;
        g_W0t[m * LEN_M + i] = fmaf(eps, sqrtf(var), mean);
    } else if (tid < EPS0_N + BTASKS) {
        int o    = tid - EPS0_N;
        int r    = o & 1;
        int lane = (o >> 1) & 31;
        int ts   = o >> 6;
        int t    = ts / NS;
        int s    = ts - t * NS;
        int g    = lane >> 2;
        int tg   = lane & 3;
        int c    = t * 8 + g;
        int k0   = s * 16 + tg * 2 + r * 8;
        float v0 = w1_at(ms, k0, c);
        float v1 = w1_at(ms, k0 + 1, c);
        __nv_bfloat16 h0 = __float2bfloat16(v0);
        __nv_bfloat16 h1 = __float2bfloat16(v1);
        uint32_t hw = (uint32_t)__bfloat16_as_ushort(h0) |
                      ((uint32_t)__bfloat16_as_ushort(h1) << 16);
        uint32_t lw = (uint32_t)__bfloat16_as_ushort(
                          __float2bfloat16(v0 - __bfloat162float(h0))) |
                      ((uint32_t)__bfloat16_as_ushort(
                          __float2bfloat16(v1 - __bfloat162float(h1))) << 16);
        int idx = ((t * NS + s) * 32 + lane) * 2 + r;
        g_Bh[idx] = hw;
        g_Bl[idx] = lw;
    } else if (tid < EPS0_N + BTASKS + TAIL_N) {
        int o = tid - (EPS0_N + BTASKS);
        float v;
        if (o < LEN_M)               v = ms[o];
        else if (o < 2 * LEN_M)      v = fabsf(ms[LEN_M + M_PRI + (o - LEN_M)]) + 1e-6f;
        else if (o < 2 * LEN_M + M_PRI) v = ms[LEN_M + (o - 2 * LEN_M)];
        else                         v = fabsf(ms[2 * LEN_M + M_PRI + (o - 2 * LEN_M - M_PRI)]) + 1e-6f;
        out[tail_base + o] = v;
    }
}

// ---------------------------------------------------------------------------
// f32x2 helpers (phase A)
// ---------------------------------------------------------------------------
typedef unsigned long long u64;
__device__ __forceinline__ u64 pk2(float a, float b) {
    u64 r; asm("mov.b64 %0, {%1, %2};" : "=l"(r) : "f"(a), "f"(b)); return r;
}
__device__ __forceinline__ void upk2(u64 v, float& a, float& b) {
    asm("mov.b64 {%0, %1}, %2;" : "=f"(a), "=f"(b) : "l"(v));
}
__device__ __forceinline__ u64 fma2(u64 a, u64 b, u64 c) {
    u64 d; asm("fma.rn.f32x2 %0, %1, %2, %3;" : "=l"(d) : "l"(a), "l"(b), "l"(c));
    return d;
}

// mma.sync m16n8k16 bf16 -> f32 accumulate (base PTX, sm_80+)
__device__ __forceinline__ void mma_bf16(float* c, const uint32_t* a,
                                         const uint32_t* b) {
    asm volatile(
        "mma.sync.aligned.m16n8k16.row.col.f32.bf16.bf16.f32 "
        "{%0,%1,%2,%3}, {%4,%5,%6,%7}, {%8,%9}, {%0,%1,%2,%3};"
        : "+f"(c[0]), "+f"(c[1]), "+f"(c[2]), "+f"(c[3])
        : "r"(a[0]), "r"(a[1]), "r"(a[2]), "r"(a[3]), "r"(b[0]), "r"(b[1]));
}

// ---------------------------------------------------------------------------
// Main kernel: block = (m, 128-n tile), 256 threads (8 warps).
// Phase A (FFMA2): z = relu(x.W0) -> bf16 hi/lo written directly as packed
//                  mma A-fragments.
// Phase B (HMMA): warp = 32 rows (2 m16 tiles) x 7-or-6 c-tiles; B fragments
//                 pre-packed -> 1 LDS.64 each; A frags -> 1 LDS.128 each.
// ---------------------------------------------------------------------------
__global__ void __launch_bounds__(256, 2)
pred_kernel(const float* __restrict__ x, float* __restrict__ out) {
    extern __shared__ __align__(16) float smem[];
    float*    sW0  = smem + OFF_W0;
    float*    sXP  = smem + OFF_XP;
    uint32_t* sAh  = reinterpret_cast<uint32_t*>(smem + OFF_AH);
    uint32_t* sAl  = reinterpret_cast<uint32_t*>(smem + OFF_AL);
    uint32_t* sBh  = reinterpret_cast<uint32_t*>(smem + OFF_BH);
    uint32_t* sBl  = reinterpret_cast<uint32_t*>(smem + OFF_BL);

    const int tid   = threadIdx.x;
    const int wid   = tid >> 5;
    const int lid   = tid & 31;
    const int m     = blockIdx.y;
    const int nbase = blockIdx.x * NT;

    // ---- fills ----
    for (int i = tid; i < LEN_M; i += 256)
        sW0[i] = g_W0t[m * LEN_M + i];
    for (int i = tid; i < NT * DDIM; i += 256) {
        int n_l = i / DDIM;
        int d   = i - n_l * DDIM;
        sXP[d * XS + nloc(n_l)] = x[(size_t)(nbase + n_l) * DDIM + d];
    }
    {
        const uint4* gh = reinterpret_cast<const uint4*>(g_Bh);
        const uint4* gl = reinterpret_cast<const uint4*>(g_Bl);
        uint4* bh = reinterpret_cast<uint4*>(sBh);
        uint4* bl = reinterpret_cast<uint4*>(sBl);
        for (int i = tid; i < BFRAG_U32 / 4; i += 256) {
            bh[i] = gh[i];
            bl[i] = gl[i];
        }
    }
    {
        // A fragments, s = 4 (bias plane): row value 1.0 at k=64, else 0
        int wb   = tid >> 5;
        int lane = tid & 31;
        int tg   = lane & 3;
        uint32_t v01 = (tg == 0) ? 0x00003F80u : 0u;
        int idx = wb * AWBS + (4 * 32 + lane) * 4;
        sAh[idx + 0] = v01;  sAh[idx + 1] = v01;
        sAh[idx + 2] = 0u;   sAh[idx + 3] = 0u;
        sAl[idx + 0] = 0u;   sAl[idx + 1] = 0u;
        sAl[idx + 2] = 0u;   sAl[idx + 3] = 0u;
    }
    __syncthreads();

    // ================= Phase A: 4h x 8n per thread ========================
    {
        const int ngr = tid & 15;          // 16 groups x 8 n
        const int hgr = tid >> 4;          // 16 groups x 4 h
        const int n0  = ngr * 8;
        const int h0  = hgr * 4;
        const int nsw = nloc(n0);

        u64 za[4][4];
#pragma unroll
        for (int i = 0; i < 4; ++i)
#pragma unroll
            for (int j = 0; j < 4; ++j) za[i][j] = 0ull;

#pragma unroll 1
        for (int d = 0; d < DDIM; ++d) {
            float4 wv = *reinterpret_cast<const float4*>(sW0 + d * D_H + h0);
            u64 ws[4];
            ws[0] = pk2(wv.x, wv.x); ws[1] = pk2(wv.y, wv.y);
            ws[2] = pk2(wv.z, wv.z); ws[3] = pk2(wv.w, wv.w);
            const float* xp = sXP + d * XS + nsw;
            ulonglong2 xq0 = *reinterpret_cast<const ulonglong2*>(xp);
            ulonglong2 xq1 = *reinterpret_cast<const ulonglong2*>(xp + 4);
            u64 xq[4] = { xq0.x, xq0.y, xq1.x, xq1.y };
#pragma unroll
            for (int i = 0; i < 4; ++i)
#pragma unroll
                for (int j = 0; j < 4; ++j)
                    za[i][j] = fma2(ws[i], xq[j], za[i][j]);
        }

        // relu + bf16 split -> packed A fragments
        // thread's rows: g = 0..7 (n0+g), hi8 = ngr&1, wb = ngr>>1
        // kpairs: p=0 -> (h0, h0+1), p=1 -> (h0+2, h0+3)
        const int wb  = ngr >> 1;
        const int hi8 = ngr & 1;
        const int s   = h0 >> 4;
        const int tg0 = (h0 >> 1) & 3;           // tg for p=0 (p=1 -> +1)
        const int khi = (h0 >> 3) & 1;
        const int reg = hi8 + 2 * khi;
#pragma unroll
        for (int j = 0; j < 4; ++j) {
            float ev[4], ov[4];
#pragma unroll
            for (int i = 0; i < 4; ++i) upk2(za[i][j], ev[i], ov[i]);
#pragma unroll
            for (int e = 0; e < 2; ++e) {
                const float* v = e ? ov : ev;
                const int g = 2 * j + e;
#pragma unroll
                for (int p = 0; p < 2; ++p) {
                    float v0 = fmaxf(v[2 * p], 0.0f);
                    float v1 = fmaxf(v[2 * p + 1], 0.0f);
                    __nv_bfloat16 b0 = __float2bfloat16(v0);
                    __nv_bfloat16 b1 = __float2bfloat16(v1);
                    uint32_t hw = (uint32_t)__bfloat16_as_ushort(b0) |
                                  ((uint32_t)__bfloat16_as_ushort(b1) << 16);
                    uint32_t lw = (uint32_t)__bfloat16_as_ushort(
                                      __float2bfloat16(v0 - __bfloat162float(b0))) |
                                  ((uint32_t)__bfloat16_as_ushort(
                                      __float2bfloat16(v1 - __bfloat162float(b1))) << 16);
                    int idx = wb * AWBS + (s * 32 + g * 4 + tg0 + p) * 4 + reg;
                    sAh[idx] = hw;
                    sAl[idx] = lw;
                }
            }
        }
    }
    __syncthreads();

    // ================= Phase B: warp-level HMMA ===========================
    const int w4    = wid & 3;             // row-block group (32 rows)
    const int tbase = (wid < 4) ? 0 : 7;
    const int tcnt  = (wid < 4) ? 7 : 6;
    const int wb0   = w4 * 2;
    const int wb1   = w4 * 2 + 1;

    float acc[2][7][4];
#pragma unroll
    for (int ti = 0; ti < 2; ++ti)
#pragma unroll
        for (int t = 0; t < 7; ++t)
#pragma unroll
            for (int q = 0; q < 4; ++q) acc[ti][t][q] = 0.0f;

#pragma unroll
    for (int s = 0; s < NS; ++s) {
        uint32_t ah0[4], al0[4], ah1[4], al1[4];
        {
            uint4 v;
            v = *reinterpret_cast<const uint4*>(sAh + wb0 * AWBS + (s * 32 + lid) * 4);
            ah0[0] = v.x; ah0[1] = v.y; ah0[2] = v.z; ah0[3] = v.w;
            v = *reinterpret_cast<const uint4*>(sAl + wb0 * AWBS + (s * 32 + lid) * 4);
            al0[0] = v.x; al0[1] = v.y; al0[2] = v.z; al0[3] = v.w;
            v = *reinterpret_cast<const uint4*>(sAh + wb1 * AWBS + (s * 32 + lid) * 4);
            ah1[0] = v.x; ah1[1] = v.y; ah1[2] = v.z; ah1[3] = v.w;
            v = *reinterpret_cast<const uint4*>(sAl + wb1 * AWBS + (s * 32 + lid) * 4);
            al1[0] = v.x; al1[1] = v.y; al1[2] = v.z; al1[3] = v.w;
        }
#pragma unroll
        for (int tt = 0; tt < 7; ++tt) {
            if (tt < tcnt) {
                const int t = tbase + tt;
                uint32_t bh[2], bl[2];
                uint2 bv;
                bv = *reinterpret_cast<const uint2*>(sBh + ((t * NS + s) * 32 + lid) * 2);
                bh[0] = bv.x; bh[1] = bv.y;
                bv = *reinterpret_cast<const uint2*>(sBl + ((t * NS + s) * 32 + lid) * 2);
                bl[0] = bv.x; bl[1] = bv.y;
                mma_bf16(acc[0][tt], ah0, bh);
                mma_bf16(acc[0][tt], ah0, bl);
                mma_bf16(acc[0][tt], al0, bh);
                mma_bf16(acc[1][tt], ah1, bh);
                mma_bf16(acc[1][tt], ah1, bl);
                mma_bf16(acc[1][tt], al1, bh);
            }
        }
    }

    // ---- store: rows w4*32 + {g, g+8, g+16, g+24}; cols (tbase+tt)*8+tg*2 --
    {
        const int g  = lid >> 2;
        const int tg = lid & 3;
        const int r0 = nbase + w4 * 32 + g;
        float* o0 = out + ((size_t)r0 * M0 + m) * M1;
        float* o1 = out + ((size_t)(r0 + 8) * M0 + m) * M1;
        float* o2 = out + ((size_t)(r0 + 16) * M0 + m) * M1;
        float* o3 = out + ((size_t)(r0 + 24) * M0 + m) * M1;
#pragma unroll
        for (int tt = 0; tt < 7; ++tt) {
            if (tt < tcnt) {
                int c = (tbase + tt) * 8 + tg * 2;
                if (c < M1) {
                    *reinterpret_cast<float2*>(o0 + c) = make_float2(acc[0][tt][0], acc[0][tt][1]);
                    *reinterpret_cast<float2*>(o1 + c) = make_float2(acc[0][tt][2], acc[0][tt][3]);
                    *reinterpret_cast<float2*>(o2 + c) = make_float2(acc[1][tt][0], acc[1][tt][1]);
                    *reinterpret_cast<float2*>(o3 + c) = make_float2(acc[1][tt][2], acc[1][tt][3]);
                }
            }
        }
    }
}

// ---------------------------------------------------------------------------
// kernel_launch
// ---------------------------------------------------------------------------
extern "C" void kernel_launch(void* const* d_in, const int* in_sizes, int n_in,
                              void* d_out, int out_size) {
    const float* x  = (const float*)d_in[0];
    const float* ms = (const float*)d_in[1];
    if (n_in >= 2 && in_sizes[0] == TAIL_N) {   // defensive input id by size
        ms = (const float*)d_in[0];
        x  = (const float*)d_in[1];
    }
    float* out = (float*)d_out;
    size_t tail_base = (size_t)out_size - TAIL_N;

    static int smem_set = 0;
    const int smem_bytes = SMEM_FLOATS * sizeof(float);
    if (!smem_set) {
        cudaFuncSetAttribute(pred_kernel,
                             cudaFuncAttributeMaxDynamicSharedMemorySize,
                             smem_bytes);
        smem_set = 1;
    }

    {
        int total = EPS0_N + BTASKS + TAIL_N;
        gen_kernel<<<(total + 255) / 256, 256>>>(ms, out, tail_base);
    }
    {
        dim3 grid(NROWS / NT, M0);
        pred_kernel<<<grid, 256, smem_bytes>>>(x, out);
    }
}

// round 15
// speedup vs baseline: 2.8065x; 1.1315x over previous
#include <cuda_runtime.h>
#include <cuda_bf16.h>
#include <cstdint>

// ---------------------------------------------------------------------------
// Problem constants
// ---------------------------------------------------------------------------
#define LEN_M   1088
#define D_H     64
#define M_PRI   65          // D_H + 1
#define M0      100
#define M1      100
#define NROWS   16384
#define DDIM    17          // DATA_DIM + 1
#define TAIL_N  (2*LEN_M + 2*M_PRI)     // 2306

#define NT      128         // n-tile per block
#define NTI     13          // c tiles (8 wide) -> 104 padded
#define NS      5           // phase-B k steps (K = 80: 64 h + bias@64 + zeros)

// A fragments: 8 wb x 5 s x 32 lanes x 4 regs, wb stride padded (bank rotate)
#define AWBS    644
#define AFRAG_U32 (8 * AWBS)              // 5152
// B fragments (phase B), hi/lo interleaved: 13 t x 5 s x 32 lanes x uint4
#define BP_N    (NTI * NS * 32)           // 2080 uint4
// W0 fragments (phase A B-operand): 8 ht x 2 ks x 32 lanes x uint4, per m
#define W0F_PER_M (8 * 2 * 32)            // 512 uint4
#define W0F_N   (M0 * W0F_PER_M)          // 51200 uint4
// X fragments (phase A A-operand): 8 wb x 2 ks x 32 lanes x 8 u32 (hi4+lo4)
#define XF_U32  (8 * 2 * 32 * 8)          // 4096

// Dynamic smem layout (u32 units):
#define OFF_AH   16
#define OFF_AL   (OFF_AH + AFRAG_U32)     //  5168
#define OFF_BP   (OFF_AL + AFRAG_U32)     // 10320  (BP_N uint4 = 8320 u32)
#define OFF_W0F  (OFF_BP + BP_N * 4)      // 18640  (2048 u32)
#define OFF_XF   (OFF_W0F + W0F_PER_M * 4)// 20688  (4096 u32)
#define SMEM_U32 (OFF_XF + XF_U32)        // 24784 u32 = 99136 B

// Scratch (pre-packed fragments)
__device__ uint4 g_Bp[BP_N];              // W1 frags {bh0,bh1,bl0,bl1}
__device__ uint4 g_W0f[W0F_N];            // W0 frags {bh0,bh1,bl0,bl1}

// ---------------------------------------------------------------------------
// Threefry-2x32 (JAX-compatible), 20 rounds
// ---------------------------------------------------------------------------
__device__ __forceinline__ uint32_t rotl32(uint32_t v, int r) {
    return (v << r) | (v >> (32 - r));
}
__device__ __forceinline__ uint2 tf2x32(uint32_t k0, uint32_t k1,
                                        uint32_t x0, uint32_t x1) {
    uint32_t ks0 = k0, ks1 = k1, ks2 = k0 ^ k1 ^ 0x1BD11BDAu;
    x0 += ks0; x1 += ks1;
#define TF_R(r) { x0 += x1; x1 = rotl32(x1, r); x1 ^= x0; }
    TF_R(13) TF_R(15) TF_R(26) TF_R(6)   x0 += ks1; x1 += ks2 + 1u;
    TF_R(17) TF_R(29) TF_R(16) TF_R(24)  x0 += ks2; x1 += ks0 + 2u;
    TF_R(13) TF_R(15) TF_R(26) TF_R(6)   x0 += ks0; x1 += ks1 + 3u;
    TF_R(17) TF_R(29) TF_R(16) TF_R(24)  x0 += ks1; x1 += ks2 + 4u;
    TF_R(13) TF_R(15) TF_R(26) TF_R(6)   x0 += ks2; x1 += ks0 + 5u;
#undef TF_R
    return make_uint2(x0, x1);
}
__device__ __forceinline__ float erfinv_xla(float x) {
    float w = -log1pf(-x * x);
    float p;
    if (w < 5.0f) {
        w -= 2.5f;
        p = 2.81022636e-08f;
        p = fmaf(p, w, 3.43273939e-07f);
        p = fmaf(p, w, -3.5233877e-06f);
        p = fmaf(p, w, -4.39150654e-06f);
        p = fmaf(p, w, 0.00021858087f);
        p = fmaf(p, w, -0.00125372503f);
        p = fmaf(p, w, -0.00417768164f);
        p = fmaf(p, w, 0.246640727f);
        p = fmaf(p, w, 1.50140941f);
    } else {
        w = sqrtf(w) - 3.0f;
        p = -0.000200214257f;
        p = fmaf(p, w, 0.000100950558f);
        p = fmaf(p, w, 0.00134934322f);
        p = fmaf(p, w, -0.00367342844f);
        p = fmaf(p, w, 0.00573950773f);
        p = fmaf(p, w, -0.0076224613f);
        p = fmaf(p, w, 0.00943887047f);
        p = fmaf(p, w, 1.00167406f);
        p = fmaf(p, w, 2.83297682f);
    }
    return p * x;
}
__device__ __forceinline__ float jax_normal_bits(uint32_t bits) {
    const float LO = __uint_as_float(0xBF7FFFFFu);
    float f = __uint_as_float((bits >> 9) | 0x3F800000u) - 1.0f;
    float u = f * 2.0f + LO;
    u = fmaxf(u, LO);
    return 1.41421356237309515f * erfinv_xla(u);
}
// W0 sample at flat row i = d*64+h, column m (key path 0)
__device__ __forceinline__ float w0_sample(const float* ms, int i, int m) {
    uint2 k = tf2x32(0u, 42u, 0u, 0u);
    uint2 r = tf2x32(k.x, k.y, 0u, (uint32_t)(i * M0 + m));
    float eps = jax_normal_bits(r.x ^ r.y);
    float mean = ms[i];
    float var  = fabsf(ms[LEN_M + M_PRI + i]) + 1e-6f;
    return fmaf(eps, sqrtf(var), mean);
}
__device__ __forceinline__ float w1_sample(const float* ms, int j, int c) {
    uint2 k = tf2x32(0u, 42u, 0u, 1u);
    uint2 r = tf2x32(k.x, k.y, 0u, (uint32_t)(j * M1 + c));
    float eps = jax_normal_bits(r.x ^ r.y);
    float mean = ms[LEN_M + j];
    float var  = fabsf(ms[2 * LEN_M + M_PRI + j]) + 1e-6f;
    return fmaf(eps, sqrtf(var), mean);
}
__device__ __forceinline__ float w1_at(const float* ms, int k, int c) {
    if (c >= M1 || k > 64) return 0.0f;
    return (k < 64) ? w1_sample(ms, k + 1, c) : w1_sample(ms, 0, c);
}
// split fp32 pair -> packed bf16 hi / lo words
__device__ __forceinline__ void splitpk(float v0, float v1,
                                        uint32_t& hw, uint32_t& lw) {
    __nv_bfloat16 b0 = __float2bfloat16(v0);
    __nv_bfloat16 b1 = __float2bfloat16(v1);
    hw = (uint32_t)__bfloat16_as_ushort(b0) |
         ((uint32_t)__bfloat16_as_ushort(b1) << 16);
    lw = (uint32_t)__bfloat16_as_ushort(
             __float2bfloat16(v0 - __bfloat162float(b0))) |
         ((uint32_t)__bfloat16_as_ushort(
             __float2bfloat16(v1 - __bfloat162float(b1))) << 16);
}

// ---------------------------------------------------------------------------
// Gen kernel: W0 fragments (per m), W1 fragments, tail outputs
// ---------------------------------------------------------------------------
__global__ void gen_kernel(const float* __restrict__ ms, float* __restrict__ out,
                           size_t tail_base) {
    int tid = blockIdx.x * blockDim.x + threadIdx.x;
    if (tid < W0F_N) {
        int o    = tid;
        int lane = o & 31;
        int ks   = (o >> 5) & 1;
        int ht   = (o >> 6) & 7;
        int m    = o >> 9;
        int g    = lane >> 2;
        int tg   = lane & 3;
        int h    = ht * 8 + g;
        uint32_t bh[2], bl[2];
#pragma unroll
        for (int r = 0; r < 2; ++r) {
            int d0 = ks * 16 + tg * 2 + r * 8;
            float v0 = (d0     < DDIM) ? w0_sample(ms, d0 * D_H + h, m) : 0.0f;
            float v1 = (d0 + 1 < DDIM) ? w0_sample(ms, (d0 + 1) * D_H + h, m) : 0.0f;
            splitpk(v0, v1, bh[r], bl[r]);
        }
        g_W0f[(m * 16 + ht * 2 + ks) * 32 + lane] =
            make_uint4(bh[0], bh[1], bl[0], bl[1]);
    } else if (tid < W0F_N + BP_N) {
        int o    = tid - W0F_N;
        int lane = o & 31;
        int rem  = o >> 5;
        int s    = rem % NS;
        int t    = rem / NS;
        int g    = lane >> 2;
        int tg   = lane & 3;
        int c    = t * 8 + g;
        uint32_t bh[2], bl[2];
#pragma unroll
        for (int r = 0; r < 2; ++r) {
            int k0 = s * 16 + tg * 2 + r * 8;
            float v0 = w1_at(ms, k0, c);
            float v1 = w1_at(ms, k0 + 1, c);
            splitpk(v0, v1, bh[r], bl[r]);
        }
        g_Bp[(t * NS + s) * 32 + lane] = make_uint4(bh[0], bh[1], bl[0], bl[1]);
    } else if (tid < W0F_N + BP_N + TAIL_N) {
        int o = tid - (W0F_N + BP_N);
        float v;
        if (o < LEN_M)               v = ms[o];
        else if (o < 2 * LEN_M)      v = fabsf(ms[LEN_M + M_PRI + (o - LEN_M)]) + 1e-6f;
        else if (o < 2 * LEN_M + M_PRI) v = ms[LEN_M + (o - 2 * LEN_M)];
        else                         v = fabsf(ms[2 * LEN_M + M_PRI + (o - 2 * LEN_M - M_PRI)]) + 1e-6f;
        out[tail_base + o] = v;
    }
}

// mma.sync m16n8k16 bf16 -> f32 accumulate (base PTX, sm_80+)
__device__ __forceinline__ void mma_bf16(float* c, const uint32_t* a,
                                         const uint32_t* b) {
    asm volatile(
        "mma.sync.aligned.m16n8k16.row.col.f32.bf16.bf16.f32 "
        "{%0,%1,%2,%3}, {%4,%5,%6,%7}, {%8,%9}, {%0,%1,%2,%3};"
        : "+f"(c[0]), "+f"(c[1]), "+f"(c[2]), "+f"(c[3])
        : "r"(a[0]), "r"(a[1]), "r"(a[2]), "r"(a[3]), "r"(b[0]), "r"(b[1]));
}

// ---------------------------------------------------------------------------
// Main kernel: block = (m, 128-n tile), 256 threads (8 warps), all-HMMA.
// Phase A: Z = relu(X.W0^T) via 3-pass split mma; accumulator fragments ARE
//          phase-B A fragments (layout identity) -> relu/split/pack/STS only.
// Phase B: as R14, with B hi/lo interleaved (1 LDS.128 per (t,s)).
// ---------------------------------------------------------------------------
__global__ void __launch_bounds__(256, 2)
pred_kernel(const float* __restrict__ x, float* __restrict__ out) {
    extern __shared__ __align__(16) uint32_t smem[];
    uint32_t* sAh  = smem + OFF_AH;
    uint32_t* sAl  = smem + OFF_AL;
    uint4*    sBp  = reinterpret_cast<uint4*>(smem + OFF_BP);
    uint4*    sW0f = reinterpret_cast<uint4*>(smem + OFF_W0F);
    uint32_t* sXf  = smem + OFF_XF;

    const int tid   = threadIdx.x;
    const int wid   = tid >> 5;
    const int lid   = tid & 31;
    const int m     = blockIdx.y;
    const int nbase = blockIdx.x * NT;

    // ---- fills ----
    {
        const uint4* src = g_W0f + m * W0F_PER_M;
        for (int i = tid; i < W0F_PER_M; i += 256) sW0f[i] = src[i];
        for (int i = tid; i < BP_N; i += 256)      sBp[i]  = g_Bp[i];
    }
    // X fragments: 512 lane-tasks, 2 per thread
#pragma unroll
    for (int ii = 0; ii < 2; ++ii) {
        int o    = tid + ii * 256;
        int lane = o & 31;
        int ks   = (o >> 5) & 1;
        int wb   = o >> 6;
        int g    = lane >> 2;
        int tg   = lane & 3;
        uint32_t xh[4], xl[4];
#pragma unroll
        for (int r = 0; r < 4; ++r) {
            int row = wb * 16 + g + (r & 1) * 8;
            int d0  = ks * 16 + tg * 2 + ((r >> 1) & 1) * 8;
            float v0 = (d0     < DDIM) ? x[(size_t)(nbase + row) * DDIM + d0] : 0.0f;
            float v1 = (d0 + 1 < DDIM) ? x[(size_t)(nbase + row) * DDIM + d0 + 1] : 0.0f;
            splitpk(v0, v1, xh[r], xl[r]);
        }
        uint32_t* p = sXf + o * 8;
        *reinterpret_cast<uint4*>(p)     = make_uint4(xh[0], xh[1], xh[2], xh[3]);
        *reinterpret_cast<uint4*>(p + 4) = make_uint4(xl[0], xl[1], xl[2], xl[3]);
    }
    // bias plane s = 4 of A fragments: k=64 -> 1.0, rest 0
    {
        int wb   = tid >> 5;
        int lane = tid & 31;
        int tg   = lane & 3;
        uint32_t v01 = (tg == 0) ? 0x00003F80u : 0u;
        int idx = wb * AWBS + (4 * 32 + lane) * 4;
        sAh[idx + 0] = v01;  sAh[idx + 1] = v01;
        sAh[idx + 2] = 0u;   sAh[idx + 3] = 0u;
        sAl[idx + 0] = 0u;   sAl[idx + 1] = 0u;
        sAl[idx + 2] = 0u;   sAl[idx + 3] = 0u;
    }
    __syncthreads();

    // ================= Phase A: warp wid owns rows wid*16..+15 ============
    {
        float acc[8][4];
#pragma unroll
        for (int t = 0; t < 8; ++t)
#pragma unroll
            for (int q = 0; q < 4; ++q) acc[t][q] = 0.0f;

#pragma unroll
        for (int ks = 0; ks < 2; ++ks) {
            const uint32_t* xp = sXf + ((wid * 2 + ks) * 32 + lid) * 8;
            uint4 vh = *reinterpret_cast<const uint4*>(xp);
            uint4 vl = *reinterpret_cast<const uint4*>(xp + 4);
            uint32_t xh[4] = { vh.x, vh.y, vh.z, vh.w };
            uint32_t xl[4] = { vl.x, vl.y, vl.z, vl.w };
#pragma unroll
            for (int ht = 0; ht < 8; ++ht) {
                uint4 wv = sW0f[(ht * 2 + ks) * 32 + lid];
                uint32_t bh[2] = { wv.x, wv.y };
                uint32_t bl[2] = { wv.z, wv.w };
                mma_bf16(acc[ht], xh, bh);
                mma_bf16(acc[ht], xh, bl);
                mma_bf16(acc[ht], xl, bh);
            }
        }

        // relu + split + pack: accumulator pair (2s, 2s+1) = A-frag for s
#pragma unroll
        for (int s = 0; s < 4; ++s) {
            float* c0 = acc[2 * s];
            float* c1 = acc[2 * s + 1];
            uint32_t ah[4], al[4];
            splitpk(fmaxf(c0[0], 0.0f), fmaxf(c0[1], 0.0f), ah[0], al[0]);
            splitpk(fmaxf(c0[2], 0.0f), fmaxf(c0[3], 0.0f), ah[1], al[1]);
            splitpk(fmaxf(c1[0], 0.0f), fmaxf(c1[1], 0.0f), ah[2], al[2]);
            splitpk(fmaxf(c1[2], 0.0f), fmaxf(c1[3], 0.0f), ah[3], al[3]);
            int idx = wid * AWBS + (s * 32 + lid) * 4;
            *reinterpret_cast<uint4*>(sAh + idx) = make_uint4(ah[0], ah[1], ah[2], ah[3]);
            *reinterpret_cast<uint4*>(sAl + idx) = make_uint4(al[0], al[1], al[2], al[3]);
        }
    }
    __syncthreads();

    // ================= Phase B: warp-level HMMA ===========================
    const int w4    = wid & 3;             // row-block group (32 rows)
    const int tbase = (wid < 4) ? 0 : 7;
    const int tcnt  = (wid < 4) ? 7 : 6;
    const int wb0   = w4 * 2;
    const int wb1   = w4 * 2 + 1;

    float acc[2][7][4];
#pragma unroll
    for (int ti = 0; ti < 2; ++ti)
#pragma unroll
        for (int t = 0; t < 7; ++t)
#pragma unroll
            for (int q = 0; q < 4; ++q) acc[ti][t][q] = 0.0f;

#pragma unroll
    for (int s = 0; s < NS; ++s) {
        uint32_t ah0[4], al0[4], ah1[4], al1[4];
        {
            uint4 v;
            v = *reinterpret_cast<const uint4*>(sAh + wb0 * AWBS + (s * 32 + lid) * 4);
            ah0[0] = v.x; ah0[1] = v.y; ah0[2] = v.z; ah0[3] = v.w;
            v = *reinterpret_cast<const uint4*>(sAl + wb0 * AWBS + (s * 32 + lid) * 4);
            al0[0] = v.x; al0[1] = v.y; al0[2] = v.z; al0[3] = v.w;
            v = *reinterpret_cast<const uint4*>(sAh + wb1 * AWBS + (s * 32 + lid) * 4);
            ah1[0] = v.x; ah1[1] = v.y; ah1[2] = v.z; ah1[3] = v.w;
            v = *reinterpret_cast<const uint4*>(sAl + wb1 * AWBS + (s * 32 + lid) * 4);
            al1[0] = v.x; al1[1] = v.y; al1[2] = v.z; al1[3] = v.w;
        }
#pragma unroll
        for (int tt = 0; tt < 7; ++tt) {
            if (tt < tcnt) {
                const int t = tbase + tt;
                uint4 bv = sBp[(t * NS + s) * 32 + lid];
                uint32_t bh[2] = { bv.x, bv.y };
                uint32_t bl[2] = { bv.z, bv.w };
                mma_bf16(acc[0][tt], ah0, bh);
                mma_bf16(acc[0][tt], ah0, bl);
                mma_bf16(acc[0][tt], al0, bh);
                mma_bf16(acc[1][tt], ah1, bh);
                mma_bf16(acc[1][tt], ah1, bl);
                mma_bf16(acc[1][tt], al1, bh);
            }
        }
    }

    // ---- store: rows w4*32 + {g, g+8, g+16, g+24}; cols (tbase+tt)*8+tg*2 --
    {
        const int g  = lid >> 2;
        const int tg = lid & 3;
        const int r0 = nbase + w4 * 32 + g;
        float* o0 = out + ((size_t)r0 * M0 + m) * M1;
        float* o1 = out + ((size_t)(r0 + 8) * M0 + m) * M1;
        float* o2 = out + ((size_t)(r0 + 16) * M0 + m) * M1;
        float* o3 = out + ((size_t)(r0 + 24) * M0 + m) * M1;
#pragma unroll
        for (int tt = 0; tt < 7; ++tt) {
            if (tt < tcnt) {
                int c = (tbase + tt) * 8 + tg * 2;
                if (c < M1) {
                    *reinterpret_cast<float2*>(o0 + c) = make_float2(acc[0][tt][0], acc[0][tt][1]);
                    *reinterpret_cast<float2*>(o1 + c) = make_float2(acc[0][tt][2], acc[0][tt][3]);
                    *reinterpret_cast<float2*>(o2 + c) = make_float2(acc[1][tt][0], acc[1][tt][1]);
                    *reinterpret_cast<float2*>(o3 + c) = make_float2(acc[1][tt][2], acc[1][tt][3]);
                }
            }
        }
    }
}

// ---------------------------------------------------------------------------
// kernel_launch
// ---------------------------------------------------------------------------
extern "C" void kernel_launch(void* const* d_in, const int* in_sizes, int n_in,
                              void* d_out, int out_size) {
    const float* x  = (const float*)d_in[0];
    const float* ms = (const float*)d_in[1];
    if (n_in >= 2 && in_sizes[0] == TAIL_N) {   // defensive input id by size
        ms = (const float*)d_in[0];
        x  = (const float*)d_in[1];
    }
    float* out = (float*)d_out;
    size_t tail_base = (size_t)out_size - TAIL_N;

    static int smem_set = 0;
    const int smem_bytes = SMEM_U32 * sizeof(uint32_t);
    if (!smem_set) {
        cudaFuncSetAttribute(pred_kernel,
                             cudaFuncAttributeMaxDynamicSharedMemorySize,
                             smem_bytes);
        smem_set = 1;
    }

    {
        int total = W0F_N + BP_N + TAIL_N;
        gen_kernel<<<(total + 255) / 256, 256>>>(ms, out, tail_base);
    }
    {
        dim3 grid(NROWS / NT, M0);
        pred_kernel<<<grid, 256, smem_bytes>>>(x, out);
    }
}

// round 16
// speedup vs baseline: 3.9485x; 1.4069x over previous
#include <cuda_runtime.h>
#include <cuda_fp16.h>
#include <cstdint>

// ---------------------------------------------------------------------------
// Problem constants
// ---------------------------------------------------------------------------
#define LEN_M   1088
#define D_H     64
#define M_PRI   65          // D_H + 1
#define M0      100
#define M1      100
#define NROWS   16384
#define DDIM    17          // DATA_DIM + 1
#define TAIL_N  (2*LEN_M + 2*M_PRI)     // 2306

#define NT      128         // n-tile per block
#define NTI     13          // c tiles (8 wide) -> 104 padded
#define NS      5           // phase-B k steps (K = 80: 64 h + bias@64 + zeros)

// A fragments (fp16, single): 8 wb x 5 s x 32 lanes x 4 regs, padded stride
#define AWBS    644
#define AFRAG_U32 (8 * AWBS)              // 5152
// B fragments (phase B): 13 t x 5 s x 32 lanes x uint2
#define BP_N    (NTI * NS * 32)           // 2080 uint2
// W0 fragments (phase A B-operand): 8 ht x 2 ks x 32 lanes x uint2, per m
#define W0F_PER_M (8 * 2 * 32)            // 512 uint2
#define W0F_N   (M0 * W0F_PER_M)          // 51200 uint2
// X fragments (phase A A-operand): 8 wb x 2 ks x 32 lanes x 4 u32
#define XF_U32  (8 * 2 * 32 * 4)          // 2048

// Dynamic smem layout (u32 units):
#define OFF_AH   16
#define OFF_BP   (OFF_AH + AFRAG_U32)       //  5168  (BP_N uint2 = 4160 u32)
#define OFF_W0F  (OFF_BP + BP_N * 2)        //  9328  (1024 u32)
#define OFF_XF   (OFF_W0F + W0F_PER_M * 2)  // 10352
#define SMEM_U32 (OFF_XF + XF_U32)          // 12400 u32 = 49600 B

// Scratch (pre-packed fp16 fragments)
__device__ uint2 g_Bp[BP_N];              // W1 frags {b0,b1}
__device__ uint2 g_W0f[W0F_N];            // W0 frags {b0,b1}

// ---------------------------------------------------------------------------
// Threefry-2x32 (JAX-compatible), 20 rounds
// ---------------------------------------------------------------------------
__device__ __forceinline__ uint32_t rotl32(uint32_t v, int r) {
    return (v << r) | (v >> (32 - r));
}
__device__ __forceinline__ uint2 tf2x32(uint32_t k0, uint32_t k1,
                                        uint32_t x0, uint32_t x1) {
    uint32_t ks0 = k0, ks1 = k1, ks2 = k0 ^ k1 ^ 0x1BD11BDAu;
    x0 += ks0; x1 += ks1;
#define TF_R(r) { x0 += x1; x1 = rotl32(x1, r); x1 ^= x0; }
    TF_R(13) TF_R(15) TF_R(26) TF_R(6)   x0 += ks1; x1 += ks2 + 1u;
    TF_R(17) TF_R(29) TF_R(16) TF_R(24)  x0 += ks2; x1 += ks0 + 2u;
    TF_R(13) TF_R(15) TF_R(26) TF_R(6)   x0 += ks0; x1 += ks1 + 3u;
    TF_R(17) TF_R(29) TF_R(16) TF_R(24)  x0 += ks1; x1 += ks2 + 4u;
    TF_R(13) TF_R(15) TF_R(26) TF_R(6)   x0 += ks2; x1 += ks0 + 5u;
#undef TF_R
    return make_uint2(x0, x1);
}
__device__ __forceinline__ float erfinv_xla(float x) {
    float w = -log1pf(-x * x);
    float p;
    if (w < 5.0f) {
        w -= 2.5f;
        p = 2.81022636e-08f;
        p = fmaf(p, w, 3.43273939e-07f);
        p = fmaf(p, w, -3.5233877e-06f);
        p = fmaf(p, w, -4.39150654e-06f);
        p = fmaf(p, w, 0.00021858087f);
        p = fmaf(p, w, -0.00125372503f);
        p = fmaf(p, w, -0.00417768164f);
        p = fmaf(p, w, 0.246640727f);
        p = fmaf(p, w, 1.50140941f);
    } else {
        w = sqrtf(w) - 3.0f;
        p = -0.000200214257f;
        p = fmaf(p, w, 0.000100950558f);
        p = fmaf(p, w, 0.00134934322f);
        p = fmaf(p, w, -0.00367342844f);
        p = fmaf(p, w, 0.00573950773f);
        p = fmaf(p, w, -0.0076224613f);
        p = fmaf(p, w, 0.00943887047f);
        p = fmaf(p, w, 1.00167406f);
        p = fmaf(p, w, 2.83297682f);
    }
    return p * x;
}
__device__ __forceinline__ float jax_normal_bits(uint32_t bits) {
    const float LO = __uint_as_float(0xBF7FFFFFu);
    float f = __uint_as_float((bits >> 9) | 0x3F800000u) - 1.0f;
    float u = f * 2.0f + LO;
    u = fmaxf(u, LO);
    return 1.41421356237309515f * erfinv_xla(u);
}
__device__ __forceinline__ float w0_sample(const float* ms, int i, int m) {
    uint2 k = tf2x32(0u, 42u, 0u, 0u);
    uint2 r = tf2x32(k.x, k.y, 0u, (uint32_t)(i * M0 + m));
    float eps = jax_normal_bits(r.x ^ r.y);
    float mean = ms[i];
    float var  = fabsf(ms[LEN_M + M_PRI + i]) + 1e-6f;
    return fmaf(eps, sqrtf(var), mean);
}
__device__ __forceinline__ float w1_sample(const float* ms, int j, int c) {
    uint2 k = tf2x32(0u, 42u, 0u, 1u);
    uint2 r = tf2x32(k.x, k.y, 0u, (uint32_t)(j * M1 + c));
    float eps = jax_normal_bits(r.x ^ r.y);
    float mean = ms[LEN_M + j];
    float var  = fabsf(ms[2 * LEN_M + M_PRI + j]) + 1e-6f;
    return fmaf(eps, sqrtf(var), mean);
}
__device__ __forceinline__ float w1_at(const float* ms, int k, int c) {
    if (c >= M1 || k > 64) return 0.0f;
    return (k < 64) ? w1_sample(ms, k + 1, c) : w1_sample(ms, 0, c);
}
// pack two floats -> fp16x2 word
__device__ __forceinline__ uint32_t pkh2(float v0, float v1) {
    __half2 h = __floats2half2_rn(v0, v1);
    return *reinterpret_cast<uint32_t*>(&h);
}

// ---------------------------------------------------------------------------
// Gen kernel: W0 fragments (per m), W1 fragments, tail outputs
// ---------------------------------------------------------------------------
__global__ void gen_kernel(const float* __restrict__ ms, float* __restrict__ out,
                           size_t tail_base) {
    int tid = blockIdx.x * blockDim.x + threadIdx.x;
    if (tid < W0F_N) {
        int o    = tid;
        int lane = o & 31;
        int ks   = (o >> 5) & 1;
        int ht   = (o >> 6) & 7;
        int m    = o >> 9;
        int g    = lane >> 2;
        int tg   = lane & 3;
        int h    = ht * 8 + g;
        uint32_t b[2];
#pragma unroll
        for (int r = 0; r < 2; ++r) {
            int d0 = ks * 16 + tg * 2 + r * 8;
            float v0 = (d0     < DDIM) ? w0_sample(ms, d0 * D_H + h, m) : 0.0f;
            float v1 = (d0 + 1 < DDIM) ? w0_sample(ms, (d0 + 1) * D_H + h, m) : 0.0f;
            b[r] = pkh2(v0, v1);
        }
        g_W0f[(m * 16 + ht * 2 + ks) * 32 + lane] = make_uint2(b[0], b[1]);
    } else if (tid < W0F_N + BP_N) {
        int o    = tid - W0F_N;
        int lane = o & 31;
        int rem  = o >> 5;
        int s    = rem % NS;
        int t    = rem / NS;
        int g    = lane >> 2;
        int tg   = lane & 3;
        int c    = t * 8 + g;
        uint32_t b[2];
#pragma unroll
        for (int r = 0; r < 2; ++r) {
            int k0 = s * 16 + tg * 2 + r * 8;
            b[r] = pkh2(w1_at(ms, k0, c), w1_at(ms, k0 + 1, c));
        }
        g_Bp[(t * NS + s) * 32 + lane] = make_uint2(b[0], b[1]);
    } else if (tid < W0F_N + BP_N + TAIL_N) {
        int o = tid - (W0F_N + BP_N);
        float v;
        if (o < LEN_M)               v = ms[o];
        else if (o < 2 * LEN_M)      v = fabsf(ms[LEN_M + M_PRI + (o - LEN_M)]) + 1e-6f;
        else if (o < 2 * LEN_M + M_PRI) v = ms[LEN_M + (o - 2 * LEN_M)];
        else                         v = fabsf(ms[2 * LEN_M + M_PRI + (o - 2 * LEN_M - M_PRI)]) + 1e-6f;
        out[tail_base + o] = v;
    }
}

// mma.sync m16n8k16 fp16 -> f32 accumulate (base PTX, sm_80+)
__device__ __forceinline__ void mma_f16(float* c, const uint32_t* a,
                                        const uint32_t* b) {
    asm volatile(
        "mma.sync.aligned.m16n8k16.row.col.f32.f16.f16.f32 "
        "{%0,%1,%2,%3}, {%4,%5,%6,%7}, {%8,%9}, {%0,%1,%2,%3};"
        : "+f"(c[0]), "+f"(c[1]), "+f"(c[2]), "+f"(c[3])
        : "r"(a[0]), "r"(a[1]), "r"(a[2]), "r"(a[3]), "r"(b[0]), "r"(b[1]));
}

// ---------------------------------------------------------------------------
// Main kernel: block = (m, 128-n tile), 256 threads (8 warps), all-HMMA fp16.
// Phase A: Z = relu(X.W0^T), single-pass fp16; accumulator fragments ARE
//          phase-B A fragments (layout identity) -> relu/pack/STS only.
// Phase B: single-pass fp16; B fragment = 1 LDS.64, A fragment = 1 LDS.128.
// ---------------------------------------------------------------------------
__global__ void __launch_bounds__(256, 3)
pred_kernel(const float* __restrict__ x, float* __restrict__ out) {
    extern __shared__ __align__(16) uint32_t smem[];
    uint32_t* sAh  = smem + OFF_AH;
    uint2*    sBp  = reinterpret_cast<uint2*>(smem + OFF_BP);
    uint2*    sW0f = reinterpret_cast<uint2*>(smem + OFF_W0F);
    uint32_t* sXf  = smem + OFF_XF;

    const int tid   = threadIdx.x;
    const int wid   = tid >> 5;
    const int lid   = tid & 31;
    const int m     = blockIdx.y;
    const int nbase = blockIdx.x * NT;

    // ---- fills ----
    {
        const uint2* src = g_W0f + m * W0F_PER_M;
        for (int i = tid; i < W0F_PER_M; i += 256) sW0f[i] = src[i];
        for (int i = tid; i < BP_N; i += 256)      sBp[i]  = g_Bp[i];
    }
    // X fragments: 512 lane-tasks, 2 per thread
#pragma unroll
    for (int ii = 0; ii < 2; ++ii) {
        int o    = tid + ii * 256;
        int lane = o & 31;
        int ks   = (o >> 5) & 1;
        int wb   = o >> 6;
        int g    = lane >> 2;
        int tg   = lane & 3;
        uint32_t xh[4];
#pragma unroll
        for (int r = 0; r < 4; ++r) {
            int row = wb * 16 + g + (r & 1) * 8;
            int d0  = ks * 16 + tg * 2 + ((r >> 1) & 1) * 8;
            float v0 = (d0     < DDIM) ? x[(size_t)(nbase + row) * DDIM + d0] : 0.0f;
            float v1 = (d0 + 1 < DDIM) ? x[(size_t)(nbase + row) * DDIM + d0 + 1] : 0.0f;
            xh[r] = pkh2(v0, v1);
        }
        *reinterpret_cast<uint4*>(sXf + o * 4) =
            make_uint4(xh[0], xh[1], xh[2], xh[3]);
    }
    // bias plane s = 4 of A fragments: k=64 -> 1.0 (fp16), rest 0
    {
        int wb   = tid >> 5;
        int lane = tid & 31;
        int tg   = lane & 3;
        uint32_t v01 = (tg == 0) ? 0x00003C00u : 0u;
        int idx = wb * AWBS + (4 * 32 + lane) * 4;
        sAh[idx + 0] = v01;  sAh[idx + 1] = v01;
        sAh[idx + 2] = 0u;   sAh[idx + 3] = 0u;
    }
    __syncthreads();

    // ================= Phase A: warp wid owns rows wid*16..+15 ============
    {
        float acc[8][4];
#pragma unroll
        for (int t = 0; t < 8; ++t)
#pragma unroll
            for (int q = 0; q < 4; ++q) acc[t][q] = 0.0f;

#pragma unroll
        for (int ks = 0; ks < 2; ++ks) {
            uint4 vh = *reinterpret_cast<const uint4*>(
                sXf + ((wid * 2 + ks) * 32 + lid) * 4);
            uint32_t xh[4] = { vh.x, vh.y, vh.z, vh.w };
#pragma unroll
            for (int ht = 0; ht < 8; ++ht) {
                uint2 wv = sW0f[(ht * 2 + ks) * 32 + lid];
                uint32_t bh[2] = { wv.x, wv.y };
                mma_f16(acc[ht], xh, bh);
            }
        }

        // relu + pack: accumulator pair (2s, 2s+1) = A-frag for k-step s
#pragma unroll
        for (int s = 0; s < 4; ++s) {
            float* c0 = acc[2 * s];
            float* c1 = acc[2 * s + 1];
            uint32_t ah[4];
            ah[0] = pkh2(fmaxf(c0[0], 0.0f), fmaxf(c0[1], 0.0f));
            ah[1] = pkh2(fmaxf(c0[2], 0.0f), fmaxf(c0[3], 0.0f));
            ah[2] = pkh2(fmaxf(c1[0], 0.0f), fmaxf(c1[1], 0.0f));
            ah[3] = pkh2(fmaxf(c1[2], 0.0f), fmaxf(c1[3], 0.0f));
            int idx = wid * AWBS + (s * 32 + lid) * 4;
            *reinterpret_cast<uint4*>(sAh + idx) =
                make_uint4(ah[0], ah[1], ah[2], ah[3]);
        }
    }
    __syncthreads();

    // ================= Phase B: warp-level HMMA ===========================
    const int w4    = wid & 3;             // row-block group (32 rows)
    const int tbase = (wid < 4) ? 0 : 7;
    const int tcnt  = (wid < 4) ? 7 : 6;
    const int wb0   = w4 * 2;
    const int wb1   = w4 * 2 + 1;

    float acc[2][7][4];
#pragma unroll
    for (int ti = 0; ti < 2; ++ti)
#pragma unroll
        for (int t = 0; t < 7; ++t)
#pragma unroll
            for (int q = 0; q < 4; ++q) acc[ti][t][q] = 0.0f;

#pragma unroll
    for (int s = 0; s < NS; ++s) {
        uint32_t a0[4], a1[4];
        {
            uint4 v;
            v = *reinterpret_cast<const uint4*>(sAh + wb0 * AWBS + (s * 32 + lid) * 4);
            a0[0] = v.x; a0[1] = v.y; a0[2] = v.z; a0[3] = v.w;
            v = *reinterpret_cast<const uint4*>(sAh + wb1 * AWBS + (s * 32 + lid) * 4);
            a1[0] = v.x; a1[1] = v.y; a1[2] = v.z; a1[3] = v.w;
        }
#pragma unroll
        for (int tt = 0; tt < 7; ++tt) {
            if (tt < tcnt) {
                const int t = tbase + tt;
                uint2 bv = sBp[(t * NS + s) * 32 + lid];
                uint32_t bh[2] = { bv.x, bv.y };
                mma_f16(acc[0][tt], a0, bh);
                mma_f16(acc[1][tt], a1, bh);
            }
        }
    }

    // ---- store: rows w4*32 + {g, g+8, g+16, g+24}; cols (tbase+tt)*8+tg*2 --
    {
        const int g  = lid >> 2;
        const int tg = lid & 3;
        const int r0 = nbase + w4 * 32 + g;
        float* o0 = out + ((size_t)r0 * M0 + m) * M1;
        float* o1 = out + ((size_t)(r0 + 8) * M0 + m) * M1;
        float* o2 = out + ((size_t)(r0 + 16) * M0 + m) * M1;
        float* o3 = out + ((size_t)(r0 + 24) * M0 + m) * M1;
#pragma unroll
        for (int tt = 0; tt < 7; ++tt) {
            if (tt < tcnt) {
                int c = (tbase + tt) * 8 + tg * 2;
                if (c < M1) {
                    *reinterpret_cast<float2*>(o0 + c) = make_float2(acc[0][tt][0], acc[0][tt][1]);
                    *reinterpret_cast<float2*>(o1 + c) = make_float2(acc[0][tt][2], acc[0][tt][3]);
                    *reinterpret_cast<float2*>(o2 + c) = make_float2(acc[1][tt][0], acc[1][tt][1]);
                    *reinterpret_cast<float2*>(o3 + c) = make_float2(acc[1][tt][2], acc[1][tt][3]);
                }
            }
        }
    }
}

// ---------------------------------------------------------------------------
// kernel_launch
// ---------------------------------------------------------------------------
extern "C" void kernel_launch(void* const* d_in, const int* in_sizes, int n_in,
                              void* d_out, int out_size) {
    const float* x  = (const float*)d_in[0];
    const float* ms = (const float*)d_in[1];
    if (n_in >= 2 && in_sizes[0] == TAIL_N) {   // defensive input id by size
        ms = (const float*)d_in[0];
        x  = (const float*)d_in[1];
    }
    float* out = (float*)d_out;
    size_t tail_base = (size_t)out_size - TAIL_N;

    static int smem_set = 0;
    const int smem_bytes = SMEM_U32 * sizeof(uint32_t);
    if (!smem_set) {
        cudaFuncSetAttribute(pred_kernel,
                             cudaFuncAttributeMaxDynamicSharedMemorySize,
                             smem_bytes);
        smem_set = 1;
    }

    {
        int total = W0F_N + BP_N + TAIL_N;
        gen_kernel<<<(total + 255) / 256, 256>>>(ms, out, tail_base);
    }
    {
        dim3 grid(NROWS / NT, M0);
        pred_kernel<<<grid, 256, smem_bytes>>>(x, out);
    }
}